// round 9
// baseline (speedup 1.0000x reference)
#include <cuda_runtime.h>
#include <cuda_bf16.h>
#include <cuda_fp16.h>
#include <cstdint>

// Problem constants
#define B_    128
#define T_    256
#define D_    384
#define H_    6
#define HD_   64
#define L_    6
#define FF_   1536
#define V_    95
#define NTOK  (B_ * T_)   // 32768

// Chunking (L2 residency): attention path in 2 chunks, FFN path in 4 chunks
#define ACH   2
#define AROWS (NTOK / ACH)   // 16384
#define FCH   4
#define FROWS (NTOK / FCH)   // 8192

extern __shared__ char dyn_smem[];

// ---------------------------------------------------------------------------
// Baseline-PTX helpers
// ---------------------------------------------------------------------------
__device__ __forceinline__ uint32_t smem_u32(const void* p) {
    uint32_t a;
    asm("{ .reg .u64 t; cvta.to.shared.u64 t, %1; cvt.u32.u64 %0, t; }"
        : "=r"(a) : "l"(p));
    return a;
}
__device__ __forceinline__ void cp16(uint32_t dst, const void* src) {
    asm volatile("cp.async.cg.shared.global [%0], [%1], 16;"
                 :: "r"(dst), "l"(src));
}
#define CP_COMMIT() asm volatile("cp.async.commit_group;" ::: "memory")
#define CP_WAIT0()  asm volatile("cp.async.wait_group 0;" ::: "memory")
#define CP_WAIT1()  asm volatile("cp.async.wait_group 1;" ::: "memory")

// m16n8k16 fp16 MMA, fp32 accumulate
__device__ __forceinline__ void mma16816(float* c, const uint32_t* a,
                                         const uint32_t* b) {
    asm volatile(
        "mma.sync.aligned.m16n8k16.row.col.f32.f16.f16.f32 "
        "{%0,%1,%2,%3},{%4,%5,%6,%7},{%8,%9},{%0,%1,%2,%3};"
        : "+f"(c[0]), "+f"(c[1]), "+f"(c[2]), "+f"(c[3])
        : "r"(a[0]), "r"(a[1]), "r"(a[2]), "r"(a[3]),
          "r"(b[0]), "r"(b[1]));
}
__device__ __forceinline__ void ldsm4(uint32_t& r0, uint32_t& r1,
                                      uint32_t& r2, uint32_t& r3, uint32_t a) {
    asm volatile("ldmatrix.sync.aligned.m8n8.x4.shared.b16 {%0,%1,%2,%3}, [%4];"
                 : "=r"(r0), "=r"(r1), "=r"(r2), "=r"(r3) : "r"(a));
}

// ---------------------------------------------------------------------------
// Weight layout (per layer, packed fp16, transposed [N][K]):
// QKV[3D x D] | WO[D x D] | W1[FF x D] | W2[D x FF]
// ---------------------------------------------------------------------------
#define S_LAYER (4 * D_ * D_ + 2 * D_ * FF_)
#define OFF_QKV 0
#define OFF_WO  (3 * D_ * D_)
#define OFF_W1  (4 * D_ * D_)
#define OFF_W2  (4 * D_ * D_ + FF_ * D_)
#define WTOT    (L_ * S_LAYER)
#define HWPAD   (128 * D_)

__device__ float g_x[NTOK * D_];
__device__ float g_q[NTOK * D_];
__device__ float g_k[NTOK * D_];
__device__ float g_v[NTOK * D_];
__device__ __half g_ah[NTOK * D_],  g_al[NTOK * D_];
__device__ __half g_fh[NTOK * FF_], g_fl[NTOK * FF_];
__device__ __half g_wh[WTOT];
__device__ __half g_hwh[HWPAD];

// ---------------------------------------------------------------------------
// Embedding
// ---------------------------------------------------------------------------
__global__ void embed_kernel(const int* __restrict__ idx,
                             const float* __restrict__ tok,
                             const float* __restrict__ pos,
                             float* __restrict__ x)
{
    int i = blockIdx.x * blockDim.x + threadIdx.x;
    if (i >= NTOK * D_) return;
    int d   = i % D_;
    int row = i / D_;
    int t   = row % T_;
    int tk  = idx[row];
    x[i] = tok[tk * D_ + d] + pos[t * D_ + d];
}

// ---------------------------------------------------------------------------
// Unified weight prep: transpose + fp16 convert, ONE launch.
// Per-layer tiles: qkv 432 | wo 144 | w1 576 | w2 576 -> 1728; +48 head tiles.
// ---------------------------------------------------------------------------
#define TILES_PER_LAYER 1728
#define TILES_WEIGHTS   (L_ * TILES_PER_LAYER)
#define TILES_TOTAL     (TILES_WEIGHTS + 48)

__global__ void prep_kernel(const float* __restrict__ wq,
                            const float* __restrict__ wk,
                            const float* __restrict__ wv,
                            const float* __restrict__ wo,
                            const float* __restrict__ w1,
                            const float* __restrict__ w2,
                            const float* __restrict__ head_w,
                            __half* __restrict__ wh,
                            __half* __restrict__ hwh)
{
    __shared__ float t[32][33];
    int bid = blockIdx.x;
    int tx = threadIdx.x, ty = threadIdx.y;

    const float* W; __half* out;
    int Kd, Nd, n0, k0, nlim;

    if (bid < TILES_WEIGHTS) {
        int layer = bid / TILES_PER_LAYER;
        int r     = bid % TILES_PER_LAYER;
        size_t lw = (size_t)layer * S_LAYER;
        if (r < 432) {                       // wq / wk / wv (144 each)
            int g = r / 144, tt = r % 144;
            W   = (g == 0 ? wq : g == 1 ? wk : wv) + (size_t)layer * D_ * D_;
            out = wh + lw + (size_t)g * D_ * D_;
            Kd = D_; Nd = D_; n0 = (tt % 12) * 32; k0 = (tt / 12) * 32;
        } else if (r < 576) {                // wo (144)
            int tt = r - 432;
            W   = wo + (size_t)layer * D_ * D_;
            out = wh + lw + OFF_WO;
            Kd = D_; Nd = D_; n0 = (tt % 12) * 32; k0 = (tt / 12) * 32;
        } else if (r < 1152) {               // w1 [D x FF] -> [FF x D] (576)
            int tt = r - 576;
            W   = w1 + (size_t)layer * D_ * FF_;
            out = wh + lw + OFF_W1;
            Kd = D_; Nd = FF_; n0 = (tt % 48) * 32; k0 = (tt / 48) * 32;
        } else {                             // w2 [FF x D] -> [D x FF] (576)
            int tt = r - 1152;
            W   = w2 + (size_t)layer * D_ * FF_;
            out = wh + lw + OFF_W2;
            Kd = FF_; Nd = D_; n0 = (tt % 12) * 32; k0 = (tt / 12) * 32;
        }
        nlim = Nd;
    } else {                                 // head: W[D][V] -> [128][D] padded
        int tt = bid - TILES_WEIGHTS;
        W   = head_w;
        out = hwh;
        Kd = D_; Nd = V_; n0 = (tt % 4) * 32; k0 = (tt / 4) * 32;
        nlim = V_;
    }

    for (int r2 = ty; r2 < 32; r2 += 8) {
        int n = n0 + tx;
        t[r2][tx] = (n < nlim) ? W[(size_t)(k0 + r2) * Nd + n] : 0.0f;
    }
    __syncthreads();
    for (int r2 = ty; r2 < 32; r2 += 8) {
        float v = t[tx][r2];
        out[(size_t)(n0 + r2) * Kd + k0 + tx] = __float2half(v);
    }
}

// ---------------------------------------------------------------------------
// Fused LayerNorm + fp16 hi/lo split (launch with chunk-offset pointers)
// ---------------------------------------------------------------------------
__global__ void __launch_bounds__(128)
lnsplit_kernel(const float* __restrict__ x,
               const float* __restrict__ gam,
               const float* __restrict__ beta,
               __half* __restrict__ hi,
               __half* __restrict__ lo)
{
    int row = blockIdx.x;
    int tid = threadIdx.x;
    const float* xr = x + (size_t)row * D_;

    float v0 = xr[tid];
    float v1 = xr[tid + 128];
    float v2 = xr[tid + 256];

    float s  = v0 + v1 + v2;
    float sq = v0 * v0 + v1 * v1 + v2 * v2;

    #pragma unroll
    for (int off = 16; off > 0; off >>= 1) {
        s  += __shfl_xor_sync(0xffffffffu, s,  off);
        sq += __shfl_xor_sync(0xffffffffu, sq, off);
    }
    __shared__ float ss[4], ssq[4];
    int w = tid >> 5;
    if ((tid & 31) == 0) { ss[w] = s; ssq[w] = sq; }
    __syncthreads();
    s  = ss[0]  + ss[1]  + ss[2]  + ss[3];
    sq = ssq[0] + ssq[1] + ssq[2] + ssq[3];

    const float invn = 1.0f / (float)D_;
    float mean = s * invn;
    float var  = sq * invn - mean * mean;
    float inv  = rsqrtf(var + 1e-5f);

    __half* hp = hi + (size_t)row * D_;
    __half* lp = lo + (size_t)row * D_;
    #pragma unroll
    for (int e = 0; e < 3; e++) {
        int   i2 = tid + e * 128;
        float vv = (e == 0) ? v0 : (e == 1) ? v1 : v2;
        float y  = (vv - mean) * inv * gam[i2] + beta[i2];
        __half h = __float2half(y);
        __half l = __float2half(y - __half2float(h));
        hp[i2] = h;
        lp[i2] = l;
    }
}

// ---------------------------------------------------------------------------
// mma.sync GEMM, fp16x2 split (A = Ah+Al, B = Bh), ldmatrix loads.
// 128x128 CTA tile, BK=32, 8 warps (4x2), warp tile 32x64.
// smem rows: 64B data + 16B pad = 80B (conflict-free ldmatrix).
// Pointers are pre-offset to the M-chunk; M = chunk rows.
// ---------------------------------------------------------------------------
#define BKG      32
#define ROWB     80
#define TILE_B   (128 * ROWB)      // 10240
#define STAGE_B  (3 * TILE_B)      // 30720 (Ah, Al, Bh)
#define GEMM_SMEM (2 * STAGE_B)    // 61440

template<bool BIAS, bool RELU, bool RESID, bool SPLITOUT>
__global__ void __launch_bounds__(256, 2)
mma_gemm(int M, int N, int K,
         const __half* __restrict__ Ah,
         const __half* __restrict__ Al,
         const __half* __restrict__ Bh,   // [N,K]
         const float* __restrict__ bias,
         float* __restrict__ C0, float* __restrict__ C1, float* __restrict__ C2,
         int nsplit, int ldc, int nmax,
         __half* __restrict__ oh, __half* __restrict__ ol)
{
    char* smem = dyn_smem;
    const uint32_t sb = smem_u32(smem);

    const int tid  = threadIdx.x;
    const int wid  = tid >> 5;
    const int lane = tid & 31;
    const int wm   = wid & 3;
    const int wn   = wid >> 2;
    const int g    = lane >> 2;
    const int t    = lane & 3;

    const int n0 = blockIdx.x * 128;
    const int m0 = blockIdx.y * 128;

    const __half* gsrc[3] = {
        Ah + (size_t)m0 * K, Al + (size_t)m0 * K, Bh + (size_t)n0 * K };

    const int KT = K / BKG;

    auto load_stage = [&](int kt, int s) {
        const uint32_t sdst = sb + s * STAGE_B;
        const int kc = kt * BKG;
        #pragma unroll
        for (int tile = 0; tile < 3; tile++) {
            const __half* gp = gsrc[tile];
            int row = tid >> 1, ch = tid & 1;
            cp16(sdst + tile * TILE_B + row * ROWB + ch * 16,
                 gp + (size_t)row * K + kc + ch * 8);
            cp16(sdst + tile * TILE_B + row * ROWB + (ch + 2) * 16,
                 gp + (size_t)row * K + kc + (ch + 2) * 8);
        }
    };

    float acc[2][8][4];
    #pragma unroll
    for (int i = 0; i < 2; i++)
        #pragma unroll
        for (int j = 0; j < 8; j++)
            #pragma unroll
            for (int c = 0; c < 4; c++) acc[i][j][c] = 0.0f;

    const uint32_t aOff = (uint32_t)((wm * 32 + (lane & 15)) * ROWB +
                                     ((lane >> 4) & 1) * 16);
    const uint32_t bOff = (uint32_t)((wn * 64 + (lane & 7) +
                                      ((lane >> 4) & 1) * 8) * ROWB +
                                     ((lane >> 3) & 1) * 16);

    load_stage(0, 0);
    CP_COMMIT();

    for (int kt = 0; kt < KT; kt++) {
        const int s = kt & 1;
        if (kt + 1 < KT) {
            load_stage(kt + 1, s ^ 1);
            CP_COMMIT();
            CP_WAIT1();
        } else {
            CP_WAIT0();
        }
        __syncthreads();

        const uint32_t base   = sb + s * STAGE_B;
        const uint32_t aBaseH = base + aOff;
        const uint32_t aBaseL = base + TILE_B + aOff;
        const uint32_t bBaseH = base + 2 * TILE_B + bOff;

        #pragma unroll
        for (int ks = 0; ks < 2; ks++) {
            uint32_t ah[2][4], al[2][4];
            #pragma unroll
            for (int i = 0; i < 2; i++) {
                ldsm4(ah[i][0], ah[i][1], ah[i][2], ah[i][3],
                      aBaseH + i * (16 * ROWB) + ks * 32);
                ldsm4(al[i][0], al[i][1], al[i][2], al[i][3],
                      aBaseL + i * (16 * ROWB) + ks * 32);
            }
            #pragma unroll
            for (int half = 0; half < 2; half++) {
                uint32_t bhr[8];
                ldsm4(bhr[0], bhr[1], bhr[2], bhr[3],
                      bBaseH + (half * 32) * ROWB + ks * 32);
                ldsm4(bhr[4], bhr[5], bhr[6], bhr[7],
                      bBaseH + (half * 32 + 16) * ROWB + ks * 32);
                #pragma unroll
                for (int i = 0; i < 2; i++)
                    #pragma unroll
                    for (int j4 = 0; j4 < 4; j4++)
                        mma16816(acc[i][half * 4 + j4], ah[i], &bhr[2 * j4]);
                #pragma unroll
                for (int i = 0; i < 2; i++)
                    #pragma unroll
                    for (int j4 = 0; j4 < 4; j4++)
                        mma16816(acc[i][half * 4 + j4], al[i], &bhr[2 * j4]);
            }
        }
        __syncthreads();
    }

    // ---- epilogue ----
    const int which = n0 / nsplit;
    const int ncol0 = n0 - which * nsplit;
    float* Cb = (which == 0) ? C0 : (which == 1) ? C1 : C2;

    #pragma unroll
    for (int i = 0; i < 2; i++) {
        const int rm = m0 + wm * 32 + i * 16 + g;
        #pragma unroll
        for (int j = 0; j < 8; j++) {
            const int cnl = ncol0 + wn * 64 + j * 8 + 2 * t;
            const int gn  = n0    + wn * 64 + j * 8 + 2 * t;
            float v00 = acc[i][j][0], v01 = acc[i][j][1];
            float v10 = acc[i][j][2], v11 = acc[i][j][3];
            if (BIAS) {
                float b0 = (gn     < nmax) ? bias[gn]     : 0.0f;
                float b1 = (gn + 1 < nmax) ? bias[gn + 1] : 0.0f;
                v00 += b0; v01 += b1; v10 += b0; v11 += b1;
            }
            if (RELU) {
                v00 = fmaxf(v00, 0.f); v01 = fmaxf(v01, 0.f);
                v10 = fmaxf(v10, 0.f); v11 = fmaxf(v11, 0.f);
            }
            if (SPLITOUT) {
                size_t p0 = (size_t)rm * ldc + cnl;
                size_t p1 = (size_t)(rm + 8) * ldc + cnl;
                __half h00 = __float2half(v00);
                __half h01 = __float2half(v01);
                __half h10 = __float2half(v10);
                __half h11 = __float2half(v11);
                __half l00 = __float2half(v00 - __half2float(h00));
                __half l01 = __float2half(v01 - __half2float(h01));
                __half l10 = __float2half(v10 - __half2float(h10));
                __half l11 = __float2half(v11 - __half2float(h11));
                *reinterpret_cast<__half2*>(oh + p0) = __half2{h00, h01};
                *reinterpret_cast<__half2*>(oh + p1) = __half2{h10, h11};
                *reinterpret_cast<__half2*>(ol + p0) = __half2{l00, l01};
                *reinterpret_cast<__half2*>(ol + p1) = __half2{l10, l11};
            } else if (nmax == N) {
                float* p0 = Cb + (size_t)rm * ldc + cnl;
                float* p1 = Cb + (size_t)(rm + 8) * ldc + cnl;
                float2 w0 = make_float2(v00, v01);
                float2 w1 = make_float2(v10, v11);
                if (RESID) {
                    float2 o0 = *reinterpret_cast<const float2*>(p0);
                    float2 o1 = *reinterpret_cast<const float2*>(p1);
                    w0.x += o0.x; w0.y += o0.y;
                    w1.x += o1.x; w1.y += o1.y;
                }
                *reinterpret_cast<float2*>(p0) = w0;
                *reinterpret_cast<float2*>(p1) = w1;
            } else {
                if (gn < nmax) {
                    Cb[(size_t)rm * ldc + cnl]       = v00;
                    Cb[(size_t)(rm + 8) * ldc + cnl] = v10;
                }
                if (gn + 1 < nmax) {
                    Cb[(size_t)rm * ldc + cnl + 1]       = v01;
                    Cb[(size_t)(rm + 8) * ldc + cnl + 1] = v11;
                }
            }
        }
    }
}

// ---------------------------------------------------------------------------
// Causal attention; pointers pre-offset to batch chunk; grid = nb*H_.
// Score loop uses 4 partial accumulators (breaks 64-deep FMA chain).
// ---------------------------------------------------------------------------
__global__ void __launch_bounds__(256)
attn_kernel(const float* __restrict__ q,
            const float* __restrict__ k,
            const float* __restrict__ v,
            __half* __restrict__ oh,
            __half* __restrict__ ol)
{
    float* smem = reinterpret_cast<float*>(dyn_smem);
    float* ks = smem;
    float* vs = smem + T_ * HD_;

    int bh = blockIdx.x;
    int b  = bh / H_;
    int h  = bh % H_;
    int tid = threadIdx.x;

    const size_t base = (size_t)(b * T_) * D_ + h * HD_;

    const float4* krow = reinterpret_cast<const float4*>(k + base + (size_t)tid * D_);
    const float4* vrow = reinterpret_cast<const float4*>(v + base + (size_t)tid * D_);
    float4* ksd = reinterpret_cast<float4*>(ks + tid * HD_);
    float4* vsd = reinterpret_cast<float4*>(vs + tid * HD_);
    #pragma unroll
    for (int d4 = 0; d4 < HD_ / 4; d4++) {
        ksd[d4] = krow[d4];
        vsd[d4] = vrow[d4];
    }
    __syncthreads();

    float qr[HD_];
    const float4* qrow = reinterpret_cast<const float4*>(q + base + (size_t)tid * D_);
    #pragma unroll
    for (int d4 = 0; d4 < HD_ / 4; d4++) {
        float4 tv = qrow[d4];
        qr[d4 * 4 + 0] = tv.x; qr[d4 * 4 + 1] = tv.y;
        qr[d4 * 4 + 2] = tv.z; qr[d4 * 4 + 3] = tv.w;
    }

    float m = -1e30f, l = 0.0f;
    float o[HD_];
    #pragma unroll
    for (int d = 0; d < HD_; d++) o[d] = 0.0f;

    const float scale = 0.125f;

    for (int j = 0; j <= tid; j++) {
        const float* kj = ks + j * HD_;
        float s0 = 0.f, s1 = 0.f, s2 = 0.f, s3 = 0.f;
        #pragma unroll
        for (int d = 0; d < HD_; d += 4) {
            s0 = fmaf(qr[d],     kj[d],     s0);
            s1 = fmaf(qr[d + 1], kj[d + 1], s1);
            s2 = fmaf(qr[d + 2], kj[d + 2], s2);
            s3 = fmaf(qr[d + 3], kj[d + 3], s3);
        }
        float s = ((s0 + s1) + (s2 + s3)) * scale;

        if (s > m) {
            float corr = __expf(m - s);
            l *= corr;
            #pragma unroll
            for (int d = 0; d < HD_; d++) o[d] *= corr;
            m = s;
        }
        float p = __expf(s - m);
        l += p;
        const float* vj = vs + j * HD_;
        #pragma unroll
        for (int d = 0; d < HD_; d++) o[d] = fmaf(p, vj[d], o[d]);
    }

    float invl = 1.0f / l;
    __half* hp = oh + base + (size_t)tid * D_;
    __half* lp = ol + base + (size_t)tid * D_;
    #pragma unroll
    for (int d = 0; d < HD_; d++) {
        float val = o[d] * invl;
        __half hh = __float2half(val);
        __half ll = __float2half(val - __half2float(hh));
        hp[d] = hh;
        lp[d] = ll;
    }
}

// ---------------------------------------------------------------------------
// Host launcher
// ---------------------------------------------------------------------------
extern "C" void kernel_launch(void* const* d_in, const int* in_sizes, int n_in,
                              void* d_out, int out_size)
{
    const int*   idx    = (const int*)  d_in[0];
    const float* tok    = (const float*)d_in[1];
    const float* pos    = (const float*)d_in[2];
    const float* ln1_s  = (const float*)d_in[3];
    const float* ln1_b  = (const float*)d_in[4];
    const float* wq     = (const float*)d_in[5];
    const float* wk     = (const float*)d_in[6];
    const float* wv     = (const float*)d_in[7];
    const float* wo     = (const float*)d_in[8];
    const float* bo     = (const float*)d_in[9];
    const float* ln2_s  = (const float*)d_in[10];
    const float* ln2_b  = (const float*)d_in[11];
    const float* w1     = (const float*)d_in[12];
    const float* b1     = (const float*)d_in[13];
    const float* w2     = (const float*)d_in[14];
    const float* b2     = (const float*)d_in[15];
    const float* lnf_s  = (const float*)d_in[16];
    const float* lnf_b  = (const float*)d_in[17];
    const float* head_w = (const float*)d_in[18];
    const float* head_b = (const float*)d_in[19];
    float* out = (float*)d_out;

    float *x, *q, *k, *v;
    __half *ah, *al, *fh, *fl, *wh, *hwh;
    cudaGetSymbolAddress((void**)&x,   g_x);
    cudaGetSymbolAddress((void**)&q,   g_q);
    cudaGetSymbolAddress((void**)&k,   g_k);
    cudaGetSymbolAddress((void**)&v,   g_v);
    cudaGetSymbolAddress((void**)&ah,  g_ah);
    cudaGetSymbolAddress((void**)&al,  g_al);
    cudaGetSymbolAddress((void**)&fh,  g_fh);
    cudaGetSymbolAddress((void**)&fl,  g_fl);
    cudaGetSymbolAddress((void**)&wh,  g_wh);
    cudaGetSymbolAddress((void**)&hwh, g_hwh);

    cudaFuncSetAttribute(attn_kernel,
                         cudaFuncAttributeMaxDynamicSharedMemorySize,
                         2 * T_ * HD_ * (int)sizeof(float));
    cudaFuncSetAttribute((const void*)mma_gemm<false, false, false, false>,
                         cudaFuncAttributeMaxDynamicSharedMemorySize, GEMM_SMEM);
    cudaFuncSetAttribute((const void*)mma_gemm<true, false, true, false>,
                         cudaFuncAttributeMaxDynamicSharedMemorySize, GEMM_SMEM);
    cudaFuncSetAttribute((const void*)mma_gemm<true, true, false, true>,
                         cudaFuncAttributeMaxDynamicSharedMemorySize, GEMM_SMEM);
    cudaFuncSetAttribute((const void*)mma_gemm<true, false, false, false>,
                         cudaFuncAttributeMaxDynamicSharedMemorySize, GEMM_SMEM);

    // [0] one-launch weight prep
    prep_kernel<<<TILES_TOTAL, dim3(32, 8)>>>(wq, wk, wv, wo, w1, w2, head_w,
                                              wh, hwh);
    // [1] embedding
    embed_kernel<<<(NTOK * D_ + 255) / 256, 256>>>(idx, tok, pos, x);

    const int attn_smem = 2 * T_ * HD_ * (int)sizeof(float);

    for (int l = 0; l < L_; l++) {
        const __half* WH = wh + (size_t)l * S_LAYER;
        const float* Bo = bo + (size_t)l * D_;
        const float* B1 = b1 + (size_t)l * FF_;
        const float* B2 = b2 + (size_t)l * D_;

        // ---- attention path: 2 chunks of AROWS tokens (whole batches) ----
        for (int c = 0; c < ACH; c++) {
            const size_t ro = (size_t)c * AROWS;         // row offset
            // ln1 + split
            lnsplit_kernel<<<AROWS, 128>>>(x + ro * D_,
                                           ln1_s + (size_t)l * D_,
                                           ln1_b + (size_t)l * D_,
                                           ah + ro * D_, al + ro * D_);
            // fused QKV (N=1152)
            mma_gemm<false, false, false, false><<<dim3(9, AROWS / 128), 256, GEMM_SMEM>>>(
                AROWS, 3 * D_, D_, ah + ro * D_, al + ro * D_, WH + OFF_QKV, nullptr,
                q + ro * D_, k + ro * D_, v + ro * D_, D_, D_, 3 * D_, nullptr, nullptr);
            // attention -> ah/al
            attn_kernel<<<(AROWS / T_) * H_, 256, attn_smem>>>(
                q + ro * D_, k + ro * D_, v + ro * D_, ah + ro * D_, al + ro * D_);
            // x += attn @ Wo + Bo
            mma_gemm<true, false, true, false><<<dim3(3, AROWS / 128), 256, GEMM_SMEM>>>(
                AROWS, D_, D_, ah + ro * D_, al + ro * D_, WH + OFF_WO, Bo,
                x + ro * D_, x + ro * D_, x + ro * D_, D_, D_, D_, nullptr, nullptr);
        }

        // ---- FFN path: 4 chunks of FROWS tokens (fh/fl stay L2-resident) ----
        for (int c = 0; c < FCH; c++) {
            const size_t ro = (size_t)c * FROWS;
            // ln2 + split
            lnsplit_kernel<<<FROWS, 128>>>(x + ro * D_,
                                           ln2_s + (size_t)l * D_,
                                           ln2_b + (size_t)l * D_,
                                           ah + ro * D_, al + ro * D_);
            // ffn = relu(h @ W1 + B1) -> split fp16 directly
            mma_gemm<true, true, false, true><<<dim3(12, FROWS / 128), 256, GEMM_SMEM>>>(
                FROWS, FF_, D_, ah + ro * D_, al + ro * D_, WH + OFF_W1, B1,
                x, x, x, FF_, FF_, FF_, fh + ro * FF_, fl + ro * FF_);
            // x += ffn @ W2 + B2
            mma_gemm<true, false, true, false><<<dim3(3, FROWS / 128), 256, GEMM_SMEM>>>(
                FROWS, D_, FF_, fh + ro * FF_, fl + ro * FF_, WH + OFF_W2, B2,
                x + ro * D_, x + ro * D_, x + ro * D_, D_, D_, D_, nullptr, nullptr);
        }
    }

    // final layernorm + split, then head GEMM (N padded to 128, guarded to 95)
    lnsplit_kernel<<<NTOK, 128>>>(x, lnf_s, lnf_b, ah, al);
    mma_gemm<true, false, false, false><<<dim3(1, 256), 256, GEMM_SMEM>>>(
        NTOK, 128, D_, ah, al, hwh, head_b,
        out, out, out, 128, V_, V_, nullptr, nullptr);
}

// round 10
// speedup vs baseline: 1.2142x; 1.2142x over previous
#include <cuda_runtime.h>
#include <cuda_bf16.h>
#include <cuda_fp16.h>
#include <cstdint>

// Problem constants
#define B_    128
#define T_    256
#define D_    384
#define H_    6
#define HD_   64
#define L_    6
#define FF_   1536
#define V_    95
#define NTOK  (B_ * T_)   // 32768

extern __shared__ char dyn_smem[];

// ---------------------------------------------------------------------------
// Baseline-PTX helpers
// ---------------------------------------------------------------------------
__device__ __forceinline__ uint32_t smem_u32(const void* p) {
    uint32_t a;
    asm("{ .reg .u64 t; cvta.to.shared.u64 t, %1; cvt.u32.u64 %0, t; }"
        : "=r"(a) : "l"(p));
    return a;
}
__device__ __forceinline__ void cp16(uint32_t dst, const void* src) {
    asm volatile("cp.async.cg.shared.global [%0], [%1], 16;"
                 :: "r"(dst), "l"(src));
}
#define CP_COMMIT() asm volatile("cp.async.commit_group;" ::: "memory")
#define CP_WAIT0()  asm volatile("cp.async.wait_group 0;" ::: "memory")
#define CP_WAIT1()  asm volatile("cp.async.wait_group 1;" ::: "memory")

// m16n8k16 fp16 MMA, fp32 accumulate
__device__ __forceinline__ void mma16816(float* c, const uint32_t* a,
                                         const uint32_t* b) {
    asm volatile(
        "mma.sync.aligned.m16n8k16.row.col.f32.f16.f16.f32 "
        "{%0,%1,%2,%3},{%4,%5,%6,%7},{%8,%9},{%0,%1,%2,%3};"
        : "+f"(c[0]), "+f"(c[1]), "+f"(c[2]), "+f"(c[3])
        : "r"(a[0]), "r"(a[1]), "r"(a[2]), "r"(a[3]),
          "r"(b[0]), "r"(b[1]));
}
__device__ __forceinline__ void ldsm4(uint32_t& r0, uint32_t& r1,
                                      uint32_t& r2, uint32_t& r3, uint32_t a) {
    asm volatile("ldmatrix.sync.aligned.m8n8.x4.shared.b16 {%0,%1,%2,%3}, [%4];"
                 : "=r"(r0), "=r"(r1), "=r"(r2), "=r"(r3) : "r"(a));
}

// ---------------------------------------------------------------------------
// Weight layout (per layer, packed fp16, transposed [N][K]):
// QKV[3D x D] | WO[D x D] | W1[FF x D] | W2[D x FF]
// ---------------------------------------------------------------------------
#define S_LAYER (4 * D_ * D_ + 2 * D_ * FF_)
#define OFF_QKV 0
#define OFF_WO  (3 * D_ * D_)
#define OFF_W1  (4 * D_ * D_)
#define OFF_W2  (4 * D_ * D_ + FF_ * D_)
#define WTOT    (L_ * S_LAYER)
#define HWPAD   (128 * D_)

__device__ float g_x[NTOK * D_];
__device__ float g_q[NTOK * D_];
__device__ float g_k[NTOK * D_];
__device__ float g_v[NTOK * D_];
__device__ __half g_ah[NTOK * D_],  g_al[NTOK * D_];
__device__ __half g_fh[NTOK * FF_];          // FFN intermediate: single fp16
__device__ __half g_wh[WTOT];
__device__ __half g_hwh[HWPAD];

// ---------------------------------------------------------------------------
// Embedding
// ---------------------------------------------------------------------------
__global__ void embed_kernel(const int* __restrict__ idx,
                             const float* __restrict__ tok,
                             const float* __restrict__ pos,
                             float* __restrict__ x)
{
    int i = blockIdx.x * blockDim.x + threadIdx.x;
    if (i >= NTOK * D_) return;
    int d   = i % D_;
    int row = i / D_;
    int t   = row % T_;
    int tk  = idx[row];
    x[i] = tok[tk * D_ + d] + pos[t * D_ + d];
}

// ---------------------------------------------------------------------------
// Unified weight prep: transpose + fp16 convert, ONE launch.
// Per-layer tiles: qkv 432 | wo 144 | w1 576 | w2 576 -> 1728; +48 head tiles.
// ---------------------------------------------------------------------------
#define TILES_PER_LAYER 1728
#define TILES_WEIGHTS   (L_ * TILES_PER_LAYER)
#define TILES_TOTAL     (TILES_WEIGHTS + 48)

__global__ void prep_kernel(const float* __restrict__ wq,
                            const float* __restrict__ wk,
                            const float* __restrict__ wv,
                            const float* __restrict__ wo,
                            const float* __restrict__ w1,
                            const float* __restrict__ w2,
                            const float* __restrict__ head_w,
                            __half* __restrict__ wh,
                            __half* __restrict__ hwh)
{
    __shared__ float t[32][33];
    int bid = blockIdx.x;
    int tx = threadIdx.x, ty = threadIdx.y;

    const float* W; __half* out;
    int Kd, Nd, n0, k0, nlim;

    if (bid < TILES_WEIGHTS) {
        int layer = bid / TILES_PER_LAYER;
        int r     = bid % TILES_PER_LAYER;
        size_t lw = (size_t)layer * S_LAYER;
        if (r < 432) {                       // wq / wk / wv (144 each)
            int g = r / 144, tt = r % 144;
            W   = (g == 0 ? wq : g == 1 ? wk : wv) + (size_t)layer * D_ * D_;
            out = wh + lw + (size_t)g * D_ * D_;
            Kd = D_; Nd = D_; n0 = (tt % 12) * 32; k0 = (tt / 12) * 32;
        } else if (r < 576) {                // wo (144)
            int tt = r - 432;
            W   = wo + (size_t)layer * D_ * D_;
            out = wh + lw + OFF_WO;
            Kd = D_; Nd = D_; n0 = (tt % 12) * 32; k0 = (tt / 12) * 32;
        } else if (r < 1152) {               // w1 [D x FF] -> [FF x D] (576)
            int tt = r - 576;
            W   = w1 + (size_t)layer * D_ * FF_;
            out = wh + lw + OFF_W1;
            Kd = D_; Nd = FF_; n0 = (tt % 48) * 32; k0 = (tt / 48) * 32;
        } else {                             // w2 [FF x D] -> [D x FF] (576)
            int tt = r - 1152;
            W   = w2 + (size_t)layer * D_ * FF_;
            out = wh + lw + OFF_W2;
            Kd = FF_; Nd = D_; n0 = (tt % 12) * 32; k0 = (tt / 12) * 32;
        }
        nlim = Nd;
    } else {                                 // head: W[D][V] -> [128][D] padded
        int tt = bid - TILES_WEIGHTS;
        W   = head_w;
        out = hwh;
        Kd = D_; Nd = V_; n0 = (tt % 4) * 32; k0 = (tt / 4) * 32;
        nlim = V_;
    }

    for (int r2 = ty; r2 < 32; r2 += 8) {
        int n = n0 + tx;
        t[r2][tx] = (n < nlim) ? W[(size_t)(k0 + r2) * Nd + n] : 0.0f;
    }
    __syncthreads();
    for (int r2 = ty; r2 < 32; r2 += 8) {
        float v = t[tx][r2];
        out[(size_t)(n0 + r2) * Kd + k0 + tx] = __float2half(v);
    }
}

// ---------------------------------------------------------------------------
// Fused LayerNorm + fp16 hi/lo split
// ---------------------------------------------------------------------------
__global__ void __launch_bounds__(128)
lnsplit_kernel(const float* __restrict__ x,
               const float* __restrict__ gam,
               const float* __restrict__ beta,
               __half* __restrict__ hi,
               __half* __restrict__ lo)
{
    int row = blockIdx.x;
    int tid = threadIdx.x;
    const float* xr = x + (size_t)row * D_;

    float v0 = xr[tid];
    float v1 = xr[tid + 128];
    float v2 = xr[tid + 256];

    float s  = v0 + v1 + v2;
    float sq = v0 * v0 + v1 * v1 + v2 * v2;

    #pragma unroll
    for (int off = 16; off > 0; off >>= 1) {
        s  += __shfl_xor_sync(0xffffffffu, s,  off);
        sq += __shfl_xor_sync(0xffffffffu, sq, off);
    }
    __shared__ float ss[4], ssq[4];
    int w = tid >> 5;
    if ((tid & 31) == 0) { ss[w] = s; ssq[w] = sq; }
    __syncthreads();
    s  = ss[0]  + ss[1]  + ss[2]  + ss[3];
    sq = ssq[0] + ssq[1] + ssq[2] + ssq[3];

    const float invn = 1.0f / (float)D_;
    float mean = s * invn;
    float var  = sq * invn - mean * mean;
    float inv  = rsqrtf(var + 1e-5f);

    __half* hp = hi + (size_t)row * D_;
    __half* lp = lo + (size_t)row * D_;
    #pragma unroll
    for (int e = 0; e < 3; e++) {
        int   i2 = tid + e * 128;
        float vv = (e == 0) ? v0 : (e == 1) ? v1 : v2;
        float y  = (vv - mean) * inv * gam[i2] + beta[i2];
        __half h = __float2half(y);
        __half l = __float2half(y - __half2float(h));
        hp[i2] = h;
        lp[i2] = l;
    }
}

// ---------------------------------------------------------------------------
// mma.sync GEMM, ldmatrix loads. DUALA: A = Ah+Al (2 products) or Ah only (1).
// 128x128 CTA tile, BK=32, 8 warps (4x2), warp tile 32x64.
// smem rows: 64B data + 16B pad = 80B (conflict-free ldmatrix).
// ---------------------------------------------------------------------------
#define BKG      32
#define ROWB     80
#define TILE_B   (128 * ROWB)      // 10240

template<bool DUALA>
struct GemmSmem { static constexpr int NT = DUALA ? 3 : 2;
                  static constexpr int STAGE = NT * TILE_B;
                  static constexpr int TOTAL = 2 * NT * TILE_B; };

template<bool BIAS, bool RELU, bool RESID, bool SPLITOUT, bool DUALA>
__global__ void __launch_bounds__(256, 2)
mma_gemm(int M, int N, int K,
         const __half* __restrict__ Ah,
         const __half* __restrict__ Al,
         const __half* __restrict__ Bh,   // [N,K]
         const float* __restrict__ bias,
         float* __restrict__ C0, float* __restrict__ C1, float* __restrict__ C2,
         int nsplit, int ldc, int nmax,
         __half* __restrict__ oh)
{
    constexpr int NT      = GemmSmem<DUALA>::NT;
    constexpr int STAGE_B = GemmSmem<DUALA>::STAGE;

    char* smem = dyn_smem;
    const uint32_t sb = smem_u32(smem);

    const int tid  = threadIdx.x;
    const int wid  = tid >> 5;
    const int lane = tid & 31;
    const int wm   = wid & 3;
    const int wn   = wid >> 2;
    const int g    = lane >> 2;
    const int t    = lane & 3;

    const int n0 = blockIdx.x * 128;
    const int m0 = blockIdx.y * 128;

    const __half* gsrc[3];
    gsrc[0] = Ah + (size_t)m0 * K;
    gsrc[1] = DUALA ? (Al + (size_t)m0 * K) : (Bh + (size_t)n0 * K);
    gsrc[2] = Bh + (size_t)n0 * K;   // only used when DUALA

    const int KT = K / BKG;

    auto load_stage = [&](int kt, int s) {
        const uint32_t sdst = sb + s * STAGE_B;
        const int kc = kt * BKG;
        #pragma unroll
        for (int tile = 0; tile < NT; tile++) {
            const __half* gp = gsrc[tile];
            int row = tid >> 1, ch = tid & 1;
            cp16(sdst + tile * TILE_B + row * ROWB + ch * 16,
                 gp + (size_t)row * K + kc + ch * 8);
            cp16(sdst + tile * TILE_B + row * ROWB + (ch + 2) * 16,
                 gp + (size_t)row * K + kc + (ch + 2) * 8);
        }
    };

    float acc[2][8][4];
    #pragma unroll
    for (int i = 0; i < 2; i++)
        #pragma unroll
        for (int j = 0; j < 8; j++)
            #pragma unroll
            for (int c = 0; c < 4; c++) acc[i][j][c] = 0.0f;

    const uint32_t aOff = (uint32_t)((wm * 32 + (lane & 15)) * ROWB +
                                     ((lane >> 4) & 1) * 16);
    const uint32_t bOff = (uint32_t)((wn * 64 + (lane & 7) +
                                      ((lane >> 4) & 1) * 8) * ROWB +
                                     ((lane >> 3) & 1) * 16);

    load_stage(0, 0);
    CP_COMMIT();

    for (int kt = 0; kt < KT; kt++) {
        const int s = kt & 1;
        if (kt + 1 < KT) {
            load_stage(kt + 1, s ^ 1);
            CP_COMMIT();
            CP_WAIT1();
        } else {
            CP_WAIT0();
        }
        __syncthreads();

        const uint32_t base   = sb + s * STAGE_B;
        const uint32_t aBaseH = base + aOff;
        const uint32_t aBaseL = base + TILE_B + aOff;          // DUALA only
        const uint32_t bBaseH = base + (NT - 1) * TILE_B + bOff;

        #pragma unroll
        for (int ks = 0; ks < 2; ks++) {
            uint32_t ah[2][4], al[2][4];
            #pragma unroll
            for (int i = 0; i < 2; i++) {
                ldsm4(ah[i][0], ah[i][1], ah[i][2], ah[i][3],
                      aBaseH + i * (16 * ROWB) + ks * 32);
                if (DUALA)
                    ldsm4(al[i][0], al[i][1], al[i][2], al[i][3],
                          aBaseL + i * (16 * ROWB) + ks * 32);
            }
            #pragma unroll
            for (int half = 0; half < 2; half++) {
                uint32_t bhr[8];
                ldsm4(bhr[0], bhr[1], bhr[2], bhr[3],
                      bBaseH + (half * 32) * ROWB + ks * 32);
                ldsm4(bhr[4], bhr[5], bhr[6], bhr[7],
                      bBaseH + (half * 32 + 16) * ROWB + ks * 32);
                #pragma unroll
                for (int i = 0; i < 2; i++)
                    #pragma unroll
                    for (int j4 = 0; j4 < 4; j4++)
                        mma16816(acc[i][half * 4 + j4], ah[i], &bhr[2 * j4]);
                if (DUALA) {
                    #pragma unroll
                    for (int i = 0; i < 2; i++)
                        #pragma unroll
                        for (int j4 = 0; j4 < 4; j4++)
                            mma16816(acc[i][half * 4 + j4], al[i], &bhr[2 * j4]);
                }
            }
        }
        __syncthreads();
    }

    // ---- epilogue ----
    const int which = n0 / nsplit;
    const int ncol0 = n0 - which * nsplit;
    float* Cb = (which == 0) ? C0 : (which == 1) ? C1 : C2;

    #pragma unroll
    for (int i = 0; i < 2; i++) {
        const int rm = m0 + wm * 32 + i * 16 + g;
        #pragma unroll
        for (int j = 0; j < 8; j++) {
            const int cnl = ncol0 + wn * 64 + j * 8 + 2 * t;
            const int gn  = n0    + wn * 64 + j * 8 + 2 * t;
            float v00 = acc[i][j][0], v01 = acc[i][j][1];
            float v10 = acc[i][j][2], v11 = acc[i][j][3];
            if (BIAS) {
                float b0 = (gn     < nmax) ? bias[gn]     : 0.0f;
                float b1 = (gn + 1 < nmax) ? bias[gn + 1] : 0.0f;
                v00 += b0; v01 += b1; v10 += b0; v11 += b1;
            }
            if (RELU) {
                v00 = fmaxf(v00, 0.f); v01 = fmaxf(v01, 0.f);
                v10 = fmaxf(v10, 0.f); v11 = fmaxf(v11, 0.f);
            }
            if (SPLITOUT) {
                size_t p0 = (size_t)rm * ldc + cnl;
                size_t p1 = (size_t)(rm + 8) * ldc + cnl;
                *reinterpret_cast<__half2*>(oh + p0) =
                    __half2{__float2half(v00), __float2half(v01)};
                *reinterpret_cast<__half2*>(oh + p1) =
                    __half2{__float2half(v10), __float2half(v11)};
            } else if (nmax == N) {
                float* p0 = Cb + (size_t)rm * ldc + cnl;
                float* p1 = Cb + (size_t)(rm + 8) * ldc + cnl;
                float2 w0 = make_float2(v00, v01);
                float2 w1 = make_float2(v10, v11);
                if (RESID) {
                    float2 o0 = *reinterpret_cast<const float2*>(p0);
                    float2 o1 = *reinterpret_cast<const float2*>(p1);
                    w0.x += o0.x; w0.y += o0.y;
                    w1.x += o1.x; w1.y += o1.y;
                }
                *reinterpret_cast<float2*>(p0) = w0;
                *reinterpret_cast<float2*>(p1) = w1;
            } else {
                if (gn < nmax) {
                    Cb[(size_t)rm * ldc + cnl]       = v00;
                    Cb[(size_t)(rm + 8) * ldc + cnl] = v10;
                }
                if (gn + 1 < nmax) {
                    Cb[(size_t)rm * ldc + cnl + 1]       = v01;
                    Cb[(size_t)(rm + 8) * ldc + cnl + 1] = v11;
                }
            }
        }
    }
}

// ---------------------------------------------------------------------------
// Causal attention; output written as split fp16 (hi/lo)
// ---------------------------------------------------------------------------
__global__ void __launch_bounds__(256)
attn_kernel(const float* __restrict__ q,
            const float* __restrict__ k,
            const float* __restrict__ v,
            __half* __restrict__ oh,
            __half* __restrict__ ol)
{
    float* smem = reinterpret_cast<float*>(dyn_smem);
    float* ks = smem;
    float* vs = smem + T_ * HD_;

    int bh = blockIdx.x;
    int b  = bh / H_;
    int h  = bh % H_;
    int tid = threadIdx.x;

    const size_t base = (size_t)(b * T_) * D_ + h * HD_;

    const float4* krow = reinterpret_cast<const float4*>(k + base + (size_t)tid * D_);
    const float4* vrow = reinterpret_cast<const float4*>(v + base + (size_t)tid * D_);
    float4* ksd = reinterpret_cast<float4*>(ks + tid * HD_);
    float4* vsd = reinterpret_cast<float4*>(vs + tid * HD_);
    #pragma unroll
    for (int d4 = 0; d4 < HD_ / 4; d4++) {
        ksd[d4] = krow[d4];
        vsd[d4] = vrow[d4];
    }
    __syncthreads();

    float qr[HD_];
    const float4* qrow = reinterpret_cast<const float4*>(q + base + (size_t)tid * D_);
    #pragma unroll
    for (int d4 = 0; d4 < HD_ / 4; d4++) {
        float4 tv = qrow[d4];
        qr[d4 * 4 + 0] = tv.x; qr[d4 * 4 + 1] = tv.y;
        qr[d4 * 4 + 2] = tv.z; qr[d4 * 4 + 3] = tv.w;
    }

    float m = -1e30f, l = 0.0f;
    float o[HD_];
    #pragma unroll
    for (int d = 0; d < HD_; d++) o[d] = 0.0f;

    const float scale = 0.125f;

    for (int j = 0; j <= tid; j++) {
        const float* kj = ks + j * HD_;
        float s0 = 0.f, s1 = 0.f, s2 = 0.f, s3 = 0.f;
        #pragma unroll
        for (int d = 0; d < HD_; d += 4) {
            s0 = fmaf(qr[d],     kj[d],     s0);
            s1 = fmaf(qr[d + 1], kj[d + 1], s1);
            s2 = fmaf(qr[d + 2], kj[d + 2], s2);
            s3 = fmaf(qr[d + 3], kj[d + 3], s3);
        }
        float s = ((s0 + s1) + (s2 + s3)) * scale;

        if (s > m) {
            float corr = __expf(m - s);
            l *= corr;
            #pragma unroll
            for (int d = 0; d < HD_; d++) o[d] *= corr;
            m = s;
        }
        float p = __expf(s - m);
        l += p;
        const float* vj = vs + j * HD_;
        #pragma unroll
        for (int d = 0; d < HD_; d++) o[d] = fmaf(p, vj[d], o[d]);
    }

    float invl = 1.0f / l;
    __half* hp = oh + base + (size_t)tid * D_;
    __half* lp = ol + base + (size_t)tid * D_;
    #pragma unroll
    for (int d = 0; d < HD_; d++) {
        float val = o[d] * invl;
        __half hh = __float2half(val);
        __half ll = __float2half(val - __half2float(hh));
        hp[d] = hh;
        lp[d] = ll;
    }
}

// ---------------------------------------------------------------------------
// Host launcher
// ---------------------------------------------------------------------------
extern "C" void kernel_launch(void* const* d_in, const int* in_sizes, int n_in,
                              void* d_out, int out_size)
{
    const int*   idx    = (const int*)  d_in[0];
    const float* tok    = (const float*)d_in[1];
    const float* pos    = (const float*)d_in[2];
    const float* ln1_s  = (const float*)d_in[3];
    const float* ln1_b  = (const float*)d_in[4];
    const float* wq     = (const float*)d_in[5];
    const float* wk     = (const float*)d_in[6];
    const float* wv     = (const float*)d_in[7];
    const float* wo     = (const float*)d_in[8];
    const float* bo     = (const float*)d_in[9];
    const float* ln2_s  = (const float*)d_in[10];
    const float* ln2_b  = (const float*)d_in[11];
    const float* w1     = (const float*)d_in[12];
    const float* b1     = (const float*)d_in[13];
    const float* w2     = (const float*)d_in[14];
    const float* b2     = (const float*)d_in[15];
    const float* lnf_s  = (const float*)d_in[16];
    const float* lnf_b  = (const float*)d_in[17];
    const float* head_w = (const float*)d_in[18];
    const float* head_b = (const float*)d_in[19];
    float* out = (float*)d_out;

    float *x, *q, *k, *v;
    __half *ah, *al, *fh, *wh, *hwh;
    cudaGetSymbolAddress((void**)&x,   g_x);
    cudaGetSymbolAddress((void**)&q,   g_q);
    cudaGetSymbolAddress((void**)&k,   g_k);
    cudaGetSymbolAddress((void**)&v,   g_v);
    cudaGetSymbolAddress((void**)&ah,  g_ah);
    cudaGetSymbolAddress((void**)&al,  g_al);
    cudaGetSymbolAddress((void**)&fh,  g_fh);
    cudaGetSymbolAddress((void**)&wh,  g_wh);
    cudaGetSymbolAddress((void**)&hwh, g_hwh);

    const int SMEM_DUAL   = GemmSmem<true>::TOTAL;    // 61440
    const int SMEM_SINGLE = GemmSmem<false>::TOTAL;   // 40960

    cudaFuncSetAttribute(attn_kernel,
                         cudaFuncAttributeMaxDynamicSharedMemorySize,
                         2 * T_ * HD_ * (int)sizeof(float));
    cudaFuncSetAttribute((const void*)mma_gemm<false, false, false, false, true>,
                         cudaFuncAttributeMaxDynamicSharedMemorySize, SMEM_DUAL);
    cudaFuncSetAttribute((const void*)mma_gemm<true, false, true, false, true>,
                         cudaFuncAttributeMaxDynamicSharedMemorySize, SMEM_DUAL);
    cudaFuncSetAttribute((const void*)mma_gemm<true, true, false, true, true>,
                         cudaFuncAttributeMaxDynamicSharedMemorySize, SMEM_DUAL);
    cudaFuncSetAttribute((const void*)mma_gemm<true, false, true, false, false>,
                         cudaFuncAttributeMaxDynamicSharedMemorySize, SMEM_SINGLE);
    cudaFuncSetAttribute((const void*)mma_gemm<true, false, false, false, true>,
                         cudaFuncAttributeMaxDynamicSharedMemorySize, SMEM_DUAL);

    // [0] one-launch weight prep
    prep_kernel<<<TILES_TOTAL, dim3(32, 8)>>>(wq, wk, wv, wo, w1, w2, head_w,
                                              wh, hwh);
    // [1] embedding
    embed_kernel<<<(NTOK * D_ + 255) / 256, 256>>>(idx, tok, pos, x);

    const int attn_smem = 2 * T_ * HD_ * (int)sizeof(float);

    for (int l = 0; l < L_; l++) {
        const __half* WH = wh + (size_t)l * S_LAYER;
        const float* Bo = bo + (size_t)l * D_;
        const float* B1 = b1 + (size_t)l * FF_;
        const float* B2 = b2 + (size_t)l * D_;

        // ln1 + split
        lnsplit_kernel<<<NTOK, 128>>>(x, ln1_s + (size_t)l * D_, ln1_b + (size_t)l * D_, ah, al);
        // fused QKV (N=1152)
        mma_gemm<false, false, false, false, true><<<dim3(9, 256), 256, SMEM_DUAL>>>(
            NTOK, 3 * D_, D_, ah, al, WH + OFF_QKV, nullptr,
            q, k, v, D_, D_, 3 * D_, nullptr);
        // attention -> ah/al
        attn_kernel<<<B_ * H_, 256, attn_smem>>>(q, k, v, ah, al);
        // x += attn @ Wo + Bo
        mma_gemm<true, false, true, false, true><<<dim3(3, 256), 256, SMEM_DUAL>>>(
            NTOK, D_, D_, ah, al, WH + OFF_WO, Bo,
            x, x, x, D_, D_, D_, nullptr);
        // ln2 + split
        lnsplit_kernel<<<NTOK, 128>>>(x, ln2_s + (size_t)l * D_, ln2_b + (size_t)l * D_, ah, al);
        // ffn = relu(h @ W1 + B1) -> single fp16
        mma_gemm<true, true, false, true, true><<<dim3(12, 256), 256, SMEM_DUAL>>>(
            NTOK, FF_, D_, ah, al, WH + OFF_W1, B1,
            x, x, x, FF_, FF_, FF_, fh);
        // x += ffn @ W2 + B2  (single-A product)
        mma_gemm<true, false, true, false, false><<<dim3(3, 256), 256, SMEM_SINGLE>>>(
            NTOK, D_, FF_, fh, nullptr, WH + OFF_W2, B2,
            x, x, x, D_, D_, D_, nullptr);
    }

    // final layernorm + split, then head GEMM (N padded to 128, guarded to 95)
    lnsplit_kernel<<<NTOK, 128>>>(x, lnf_s, lnf_b, ah, al);
    mma_gemm<true, false, false, false, true><<<dim3(1, 256), 256, SMEM_DUAL>>>(
        NTOK, 128, D_, ah, al, hwh, head_b,
        out, out, out, 128, V_, V_, nullptr);
}

// round 11
// speedup vs baseline: 1.2933x; 1.0651x over previous
#include <cuda_runtime.h>
#include <cuda_bf16.h>
#include <cuda_fp16.h>
#include <cstdint>

// Problem constants
#define B_    128
#define T_    256
#define D_    384
#define H_    6
#define HD_   64
#define L_    6
#define FF_   1536
#define V_    95
#define NTOK  (B_ * T_)   // 32768

extern __shared__ char dyn_smem[];

// ---------------------------------------------------------------------------
// Baseline-PTX helpers
// ---------------------------------------------------------------------------
__device__ __forceinline__ uint32_t smem_u32(const void* p) {
    uint32_t a;
    asm("{ .reg .u64 t; cvta.to.shared.u64 t, %1; cvt.u32.u64 %0, t; }"
        : "=r"(a) : "l"(p));
    return a;
}
__device__ __forceinline__ void cp16(uint32_t dst, const void* src) {
    asm volatile("cp.async.cg.shared.global [%0], [%1], 16;"
                 :: "r"(dst), "l"(src));
}
#define CP_COMMIT() asm volatile("cp.async.commit_group;" ::: "memory")
#define CP_WAIT0()  asm volatile("cp.async.wait_group 0;" ::: "memory")
#define CP_WAIT1()  asm volatile("cp.async.wait_group 1;" ::: "memory")

// m16n8k16 fp16 MMA, fp32 accumulate
__device__ __forceinline__ void mma16816(float* c, const uint32_t* a,
                                         const uint32_t* b) {
    asm volatile(
        "mma.sync.aligned.m16n8k16.row.col.f32.f16.f16.f32 "
        "{%0,%1,%2,%3},{%4,%5,%6,%7},{%8,%9},{%0,%1,%2,%3};"
        : "+f"(c[0]), "+f"(c[1]), "+f"(c[2]), "+f"(c[3])
        : "r"(a[0]), "r"(a[1]), "r"(a[2]), "r"(a[3]),
          "r"(b[0]), "r"(b[1]));
}
__device__ __forceinline__ void ldsm4(uint32_t& r0, uint32_t& r1,
                                      uint32_t& r2, uint32_t& r3, uint32_t a) {
    asm volatile("ldmatrix.sync.aligned.m8n8.x4.shared.b16 {%0,%1,%2,%3}, [%4];"
                 : "=r"(r0), "=r"(r1), "=r"(r2), "=r"(r3) : "r"(a));
}

// ---------------------------------------------------------------------------
// Weight layout (per layer, packed fp16, transposed [N][K]):
// QKV[3D x D] | WO[D x D] | W1[FF x D] | W2[D x FF]
// ---------------------------------------------------------------------------
#define S_LAYER (4 * D_ * D_ + 2 * D_ * FF_)
#define OFF_QKV 0
#define OFF_WO  (3 * D_ * D_)
#define OFF_W1  (4 * D_ * D_)
#define OFF_W2  (4 * D_ * D_ + FF_ * D_)
#define WTOT    (L_ * S_LAYER)
#define HWPAD   (128 * D_)

__device__ float g_x[NTOK * D_];
__device__ float g_q[NTOK * D_];
__device__ float g_k[NTOK * D_];
__device__ float g_v[NTOK * D_];
__device__ __half g_ah[NTOK * D_],  g_al[NTOK * D_];
__device__ __half g_fh[NTOK * FF_];          // FFN intermediate: single fp16
__device__ __half g_wh[WTOT];
__device__ __half g_hwh[HWPAD];

// ---------------------------------------------------------------------------
// Embedding
// ---------------------------------------------------------------------------
__global__ void embed_kernel(const int* __restrict__ idx,
                             const float* __restrict__ tok,
                             const float* __restrict__ pos,
                             float* __restrict__ x)
{
    int i = blockIdx.x * blockDim.x + threadIdx.x;
    if (i >= NTOK * D_) return;
    int d   = i % D_;
    int row = i / D_;
    int t   = row % T_;
    int tk  = idx[row];
    x[i] = tok[tk * D_ + d] + pos[t * D_ + d];
}

// ---------------------------------------------------------------------------
// Unified weight prep: transpose + fp16 convert, ONE launch.
// Per-layer tiles: qkv 432 | wo 144 | w1 576 | w2 576 -> 1728; +48 head tiles.
// ---------------------------------------------------------------------------
#define TILES_PER_LAYER 1728
#define TILES_WEIGHTS   (L_ * TILES_PER_LAYER)
#define TILES_TOTAL     (TILES_WEIGHTS + 48)

__global__ void prep_kernel(const float* __restrict__ wq,
                            const float* __restrict__ wk,
                            const float* __restrict__ wv,
                            const float* __restrict__ wo,
                            const float* __restrict__ w1,
                            const float* __restrict__ w2,
                            const float* __restrict__ head_w,
                            __half* __restrict__ wh,
                            __half* __restrict__ hwh)
{
    __shared__ float t[32][33];
    int bid = blockIdx.x;
    int tx = threadIdx.x, ty = threadIdx.y;

    const float* W; __half* out;
    int Kd, Nd, n0, k0, nlim;

    if (bid < TILES_WEIGHTS) {
        int layer = bid / TILES_PER_LAYER;
        int r     = bid % TILES_PER_LAYER;
        size_t lw = (size_t)layer * S_LAYER;
        if (r < 432) {                       // wq / wk / wv (144 each)
            int g = r / 144, tt = r % 144;
            W   = (g == 0 ? wq : g == 1 ? wk : wv) + (size_t)layer * D_ * D_;
            out = wh + lw + (size_t)g * D_ * D_;
            Kd = D_; Nd = D_; n0 = (tt % 12) * 32; k0 = (tt / 12) * 32;
        } else if (r < 576) {                // wo (144)
            int tt = r - 432;
            W   = wo + (size_t)layer * D_ * D_;
            out = wh + lw + OFF_WO;
            Kd = D_; Nd = D_; n0 = (tt % 12) * 32; k0 = (tt / 12) * 32;
        } else if (r < 1152) {               // w1 [D x FF] -> [FF x D] (576)
            int tt = r - 576;
            W   = w1 + (size_t)layer * D_ * FF_;
            out = wh + lw + OFF_W1;
            Kd = D_; Nd = FF_; n0 = (tt % 48) * 32; k0 = (tt / 48) * 32;
        } else {                             // w2 [FF x D] -> [D x FF] (576)
            int tt = r - 1152;
            W   = w2 + (size_t)layer * D_ * FF_;
            out = wh + lw + OFF_W2;
            Kd = FF_; Nd = D_; n0 = (tt % 12) * 32; k0 = (tt / 12) * 32;
        }
        nlim = Nd;
    } else {                                 // head: W[D][V] -> [128][D] padded
        int tt = bid - TILES_WEIGHTS;
        W   = head_w;
        out = hwh;
        Kd = D_; Nd = V_; n0 = (tt % 4) * 32; k0 = (tt / 4) * 32;
        nlim = V_;
    }

    for (int r2 = ty; r2 < 32; r2 += 8) {
        int n = n0 + tx;
        t[r2][tx] = (n < nlim) ? W[(size_t)(k0 + r2) * Nd + n] : 0.0f;
    }
    __syncthreads();
    for (int r2 = ty; r2 < 32; r2 += 8) {
        float v = t[tx][r2];
        out[(size_t)(n0 + r2) * Kd + k0 + tx] = __float2half(v);
    }
}

// ---------------------------------------------------------------------------
// Fused LayerNorm + fp16 split; WRITELO controls whether lo-half is stored.
// ---------------------------------------------------------------------------
template<bool WRITELO>
__global__ void __launch_bounds__(128)
lnsplit_kernel(const float* __restrict__ x,
               const float* __restrict__ gam,
               const float* __restrict__ beta,
               __half* __restrict__ hi,
               __half* __restrict__ lo)
{
    int row = blockIdx.x;
    int tid = threadIdx.x;
    const float* xr = x + (size_t)row * D_;

    float v0 = xr[tid];
    float v1 = xr[tid + 128];
    float v2 = xr[tid + 256];

    float s  = v0 + v1 + v2;
    float sq = v0 * v0 + v1 * v1 + v2 * v2;

    #pragma unroll
    for (int off = 16; off > 0; off >>= 1) {
        s  += __shfl_xor_sync(0xffffffffu, s,  off);
        sq += __shfl_xor_sync(0xffffffffu, sq, off);
    }
    __shared__ float ss[4], ssq[4];
    int w = tid >> 5;
    if ((tid & 31) == 0) { ss[w] = s; ssq[w] = sq; }
    __syncthreads();
    s  = ss[0]  + ss[1]  + ss[2]  + ss[3];
    sq = ssq[0] + ssq[1] + ssq[2] + ssq[3];

    const float invn = 1.0f / (float)D_;
    float mean = s * invn;
    float var  = sq * invn - mean * mean;
    float inv  = rsqrtf(var + 1e-5f);

    __half* hp = hi + (size_t)row * D_;
    __half* lp = lo + (size_t)row * D_;
    #pragma unroll
    for (int e = 0; e < 3; e++) {
        int   i2 = tid + e * 128;
        float vv = (e == 0) ? v0 : (e == 1) ? v1 : v2;
        float y  = (vv - mean) * inv * gam[i2] + beta[i2];
        __half h = __float2half(y);
        hp[i2] = h;
        if (WRITELO)
            lp[i2] = __float2half(y - __half2float(h));
    }
}

// ---------------------------------------------------------------------------
// mma.sync GEMM, ldmatrix loads. DUALA: A = Ah+Al (2 products) or Ah only (1).
// 128x128 CTA tile, BK=32, 8 warps (4x2), warp tile 32x64.
// smem rows: 64B data + 16B pad = 80B (conflict-free ldmatrix).
// ---------------------------------------------------------------------------
#define BKG      32
#define ROWB     80
#define TILE_B   (128 * ROWB)      // 10240

template<bool DUALA>
struct GemmSmem { static constexpr int NT = DUALA ? 3 : 2;
                  static constexpr int STAGE = NT * TILE_B;
                  static constexpr int TOTAL = 2 * NT * TILE_B; };

template<bool BIAS, bool RELU, bool RESID, bool SPLITOUT, bool DUALA>
__global__ void __launch_bounds__(256, 2)
mma_gemm(int M, int N, int K,
         const __half* __restrict__ Ah,
         const __half* __restrict__ Al,
         const __half* __restrict__ Bh,   // [N,K]
         const float* __restrict__ bias,
         float* __restrict__ C0, float* __restrict__ C1, float* __restrict__ C2,
         int nsplit, int ldc, int nmax,
         __half* __restrict__ oh)
{
    constexpr int NT      = GemmSmem<DUALA>::NT;
    constexpr int STAGE_B = GemmSmem<DUALA>::STAGE;

    char* smem = dyn_smem;
    const uint32_t sb = smem_u32(smem);

    const int tid  = threadIdx.x;
    const int wid  = tid >> 5;
    const int lane = tid & 31;
    const int wm   = wid & 3;
    const int wn   = wid >> 2;
    const int g    = lane >> 2;
    const int t    = lane & 3;

    const int n0 = blockIdx.x * 128;
    const int m0 = blockIdx.y * 128;

    const __half* gsrc[3];
    gsrc[0] = Ah + (size_t)m0 * K;
    gsrc[1] = DUALA ? (Al + (size_t)m0 * K) : (Bh + (size_t)n0 * K);
    gsrc[2] = Bh + (size_t)n0 * K;   // only used when DUALA

    const int KT = K / BKG;

    auto load_stage = [&](int kt, int s) {
        const uint32_t sdst = sb + s * STAGE_B;
        const int kc = kt * BKG;
        #pragma unroll
        for (int tile = 0; tile < NT; tile++) {
            const __half* gp = gsrc[tile];
            int row = tid >> 1, ch = tid & 1;
            cp16(sdst + tile * TILE_B + row * ROWB + ch * 16,
                 gp + (size_t)row * K + kc + ch * 8);
            cp16(sdst + tile * TILE_B + row * ROWB + (ch + 2) * 16,
                 gp + (size_t)row * K + kc + (ch + 2) * 8);
        }
    };

    float acc[2][8][4];
    #pragma unroll
    for (int i = 0; i < 2; i++)
        #pragma unroll
        for (int j = 0; j < 8; j++)
            #pragma unroll
            for (int c = 0; c < 4; c++) acc[i][j][c] = 0.0f;

    const uint32_t aOff = (uint32_t)((wm * 32 + (lane & 15)) * ROWB +
                                     ((lane >> 4) & 1) * 16);
    const uint32_t bOff = (uint32_t)((wn * 64 + (lane & 7) +
                                      ((lane >> 4) & 1) * 8) * ROWB +
                                     ((lane >> 3) & 1) * 16);

    load_stage(0, 0);
    CP_COMMIT();

    for (int kt = 0; kt < KT; kt++) {
        const int s = kt & 1;
        if (kt + 1 < KT) {
            load_stage(kt + 1, s ^ 1);
            CP_COMMIT();
            CP_WAIT1();
        } else {
            CP_WAIT0();
        }
        __syncthreads();

        const uint32_t base   = sb + s * STAGE_B;
        const uint32_t aBaseH = base + aOff;
        const uint32_t aBaseL = base + TILE_B + aOff;          // DUALA only
        const uint32_t bBaseH = base + (NT - 1) * TILE_B + bOff;

        #pragma unroll
        for (int ks = 0; ks < 2; ks++) {
            uint32_t ah[2][4], al[2][4];
            #pragma unroll
            for (int i = 0; i < 2; i++) {
                ldsm4(ah[i][0], ah[i][1], ah[i][2], ah[i][3],
                      aBaseH + i * (16 * ROWB) + ks * 32);
                if (DUALA)
                    ldsm4(al[i][0], al[i][1], al[i][2], al[i][3],
                          aBaseL + i * (16 * ROWB) + ks * 32);
            }
            #pragma unroll
            for (int half = 0; half < 2; half++) {
                uint32_t bhr[8];
                ldsm4(bhr[0], bhr[1], bhr[2], bhr[3],
                      bBaseH + (half * 32) * ROWB + ks * 32);
                ldsm4(bhr[4], bhr[5], bhr[6], bhr[7],
                      bBaseH + (half * 32 + 16) * ROWB + ks * 32);
                #pragma unroll
                for (int i = 0; i < 2; i++)
                    #pragma unroll
                    for (int j4 = 0; j4 < 4; j4++)
                        mma16816(acc[i][half * 4 + j4], ah[i], &bhr[2 * j4]);
                if (DUALA) {
                    #pragma unroll
                    for (int i = 0; i < 2; i++)
                        #pragma unroll
                        for (int j4 = 0; j4 < 4; j4++)
                            mma16816(acc[i][half * 4 + j4], al[i], &bhr[2 * j4]);
                }
            }
        }
        __syncthreads();
    }

    // ---- epilogue ----
    const int which = n0 / nsplit;
    const int ncol0 = n0 - which * nsplit;
    float* Cb = (which == 0) ? C0 : (which == 1) ? C1 : C2;

    #pragma unroll
    for (int i = 0; i < 2; i++) {
        const int rm = m0 + wm * 32 + i * 16 + g;
        #pragma unroll
        for (int j = 0; j < 8; j++) {
            const int cnl = ncol0 + wn * 64 + j * 8 + 2 * t;
            const int gn  = n0    + wn * 64 + j * 8 + 2 * t;
            float v00 = acc[i][j][0], v01 = acc[i][j][1];
            float v10 = acc[i][j][2], v11 = acc[i][j][3];
            if (BIAS) {
                float b0 = (gn     < nmax) ? bias[gn]     : 0.0f;
                float b1 = (gn + 1 < nmax) ? bias[gn + 1] : 0.0f;
                v00 += b0; v01 += b1; v10 += b0; v11 += b1;
            }
            if (RELU) {
                v00 = fmaxf(v00, 0.f); v01 = fmaxf(v01, 0.f);
                v10 = fmaxf(v10, 0.f); v11 = fmaxf(v11, 0.f);
            }
            if (SPLITOUT) {
                size_t p0 = (size_t)rm * ldc + cnl;
                size_t p1 = (size_t)(rm + 8) * ldc + cnl;
                *reinterpret_cast<__half2*>(oh + p0) =
                    __half2{__float2half(v00), __float2half(v01)};
                *reinterpret_cast<__half2*>(oh + p1) =
                    __half2{__float2half(v10), __float2half(v11)};
            } else if (nmax == N) {
                float* p0 = Cb + (size_t)rm * ldc + cnl;
                float* p1 = Cb + (size_t)(rm + 8) * ldc + cnl;
                float2 w0 = make_float2(v00, v01);
                float2 w1 = make_float2(v10, v11);
                if (RESID) {
                    float2 o0 = *reinterpret_cast<const float2*>(p0);
                    float2 o1 = *reinterpret_cast<const float2*>(p1);
                    w0.x += o0.x; w0.y += o0.y;
                    w1.x += o1.x; w1.y += o1.y;
                }
                *reinterpret_cast<float2*>(p0) = w0;
                *reinterpret_cast<float2*>(p1) = w1;
            } else {
                if (gn < nmax) {
                    Cb[(size_t)rm * ldc + cnl]       = v00;
                    Cb[(size_t)(rm + 8) * ldc + cnl] = v10;
                }
                if (gn + 1 < nmax) {
                    Cb[(size_t)rm * ldc + cnl + 1]       = v01;
                    Cb[(size_t)(rm + 8) * ldc + cnl + 1] = v11;
                }
            }
        }
    }
}

// ---------------------------------------------------------------------------
// Causal attention; output written as split fp16 (hi/lo)
// ---------------------------------------------------------------------------
__global__ void __launch_bounds__(256)
attn_kernel(const float* __restrict__ q,
            const float* __restrict__ k,
            const float* __restrict__ v,
            __half* __restrict__ oh,
            __half* __restrict__ ol)
{
    float* smem = reinterpret_cast<float*>(dyn_smem);
    float* ks = smem;
    float* vs = smem + T_ * HD_;

    int bh = blockIdx.x;
    int b  = bh / H_;
    int h  = bh % H_;
    int tid = threadIdx.x;

    const size_t base = (size_t)(b * T_) * D_ + h * HD_;

    const float4* krow = reinterpret_cast<const float4*>(k + base + (size_t)tid * D_);
    const float4* vrow = reinterpret_cast<const float4*>(v + base + (size_t)tid * D_);
    float4* ksd = reinterpret_cast<float4*>(ks + tid * HD_);
    float4* vsd = reinterpret_cast<float4*>(vs + tid * HD_);
    #pragma unroll
    for (int d4 = 0; d4 < HD_ / 4; d4++) {
        ksd[d4] = krow[d4];
        vsd[d4] = vrow[d4];
    }
    __syncthreads();

    float qr[HD_];
    const float4* qrow = reinterpret_cast<const float4*>(q + base + (size_t)tid * D_);
    #pragma unroll
    for (int d4 = 0; d4 < HD_ / 4; d4++) {
        float4 tv = qrow[d4];
        qr[d4 * 4 + 0] = tv.x; qr[d4 * 4 + 1] = tv.y;
        qr[d4 * 4 + 2] = tv.z; qr[d4 * 4 + 3] = tv.w;
    }

    float m = -1e30f, l = 0.0f;
    float o[HD_];
    #pragma unroll
    for (int d = 0; d < HD_; d++) o[d] = 0.0f;

    const float scale = 0.125f;

    for (int j = 0; j <= tid; j++) {
        const float* kj = ks + j * HD_;
        float s0 = 0.f, s1 = 0.f, s2 = 0.f, s3 = 0.f;
        #pragma unroll
        for (int d = 0; d < HD_; d += 4) {
            s0 = fmaf(qr[d],     kj[d],     s0);
            s1 = fmaf(qr[d + 1], kj[d + 1], s1);
            s2 = fmaf(qr[d + 2], kj[d + 2], s2);
            s3 = fmaf(qr[d + 3], kj[d + 3], s3);
        }
        float s = ((s0 + s1) + (s2 + s3)) * scale;

        if (s > m) {
            float corr = __expf(m - s);
            l *= corr;
            #pragma unroll
            for (int d = 0; d < HD_; d++) o[d] *= corr;
            m = s;
        }
        float p = __expf(s - m);
        l += p;
        const float* vj = vs + j * HD_;
        #pragma unroll
        for (int d = 0; d < HD_; d++) o[d] = fmaf(p, vj[d], o[d]);
    }

    float invl = 1.0f / l;
    __half* hp = oh + base + (size_t)tid * D_;
    __half* lp = ol + base + (size_t)tid * D_;
    #pragma unroll
    for (int d = 0; d < HD_; d++) {
        float val = o[d] * invl;
        __half hh = __float2half(val);
        __half ll = __float2half(val - __half2float(hh));
        hp[d] = hh;
        lp[d] = ll;
    }
}

// ---------------------------------------------------------------------------
// Host launcher
// ---------------------------------------------------------------------------
extern "C" void kernel_launch(void* const* d_in, const int* in_sizes, int n_in,
                              void* d_out, int out_size)
{
    const int*   idx    = (const int*)  d_in[0];
    const float* tok    = (const float*)d_in[1];
    const float* pos    = (const float*)d_in[2];
    const float* ln1_s  = (const float*)d_in[3];
    const float* ln1_b  = (const float*)d_in[4];
    const float* wq     = (const float*)d_in[5];
    const float* wk     = (const float*)d_in[6];
    const float* wv     = (const float*)d_in[7];
    const float* wo     = (const float*)d_in[8];
    const float* bo     = (const float*)d_in[9];
    const float* ln2_s  = (const float*)d_in[10];
    const float* ln2_b  = (const float*)d_in[11];
    const float* w1     = (const float*)d_in[12];
    const float* b1     = (const float*)d_in[13];
    const float* w2     = (const float*)d_in[14];
    const float* b2     = (const float*)d_in[15];
    const float* lnf_s  = (const float*)d_in[16];
    const float* lnf_b  = (const float*)d_in[17];
    const float* head_w = (const float*)d_in[18];
    const float* head_b = (const float*)d_in[19];
    float* out = (float*)d_out;

    float *x, *q, *k, *v;
    __half *ah, *al, *fh, *wh, *hwh;
    cudaGetSymbolAddress((void**)&x,   g_x);
    cudaGetSymbolAddress((void**)&q,   g_q);
    cudaGetSymbolAddress((void**)&k,   g_k);
    cudaGetSymbolAddress((void**)&v,   g_v);
    cudaGetSymbolAddress((void**)&ah,  g_ah);
    cudaGetSymbolAddress((void**)&al,  g_al);
    cudaGetSymbolAddress((void**)&fh,  g_fh);
    cudaGetSymbolAddress((void**)&wh,  g_wh);
    cudaGetSymbolAddress((void**)&hwh, g_hwh);

    const int SMEM_DUAL   = GemmSmem<true>::TOTAL;    // 61440
    const int SMEM_SINGLE = GemmSmem<false>::TOTAL;   // 40960

    cudaFuncSetAttribute(attn_kernel,
                         cudaFuncAttributeMaxDynamicSharedMemorySize,
                         2 * T_ * HD_ * (int)sizeof(float));
    cudaFuncSetAttribute((const void*)mma_gemm<false, false, false, false, true>,
                         cudaFuncAttributeMaxDynamicSharedMemorySize, SMEM_DUAL);
    cudaFuncSetAttribute((const void*)mma_gemm<true, false, true, false, true>,
                         cudaFuncAttributeMaxDynamicSharedMemorySize, SMEM_DUAL);
    cudaFuncSetAttribute((const void*)mma_gemm<true, true, false, true, false>,
                         cudaFuncAttributeMaxDynamicSharedMemorySize, SMEM_SINGLE);
    cudaFuncSetAttribute((const void*)mma_gemm<true, false, true, false, false>,
                         cudaFuncAttributeMaxDynamicSharedMemorySize, SMEM_SINGLE);
    cudaFuncSetAttribute((const void*)mma_gemm<true, false, false, false, true>,
                         cudaFuncAttributeMaxDynamicSharedMemorySize, SMEM_DUAL);

    // [0] one-launch weight prep
    prep_kernel<<<TILES_TOTAL, dim3(32, 8)>>>(wq, wk, wv, wo, w1, w2, head_w,
                                              wh, hwh);
    // [1] embedding
    embed_kernel<<<(NTOK * D_ + 255) / 256, 256>>>(idx, tok, pos, x);

    const int attn_smem = 2 * T_ * HD_ * (int)sizeof(float);

    for (int l = 0; l < L_; l++) {
        const __half* WH = wh + (size_t)l * S_LAYER;
        const float* Bo = bo + (size_t)l * D_;
        const float* B1 = b1 + (size_t)l * FF_;
        const float* B2 = b2 + (size_t)l * D_;

        // ln1 + split (dual: feeds QKV dual-A)
        lnsplit_kernel<true><<<NTOK, 128>>>(x, ln1_s + (size_t)l * D_,
                                            ln1_b + (size_t)l * D_, ah, al);
        // fused QKV (N=1152), dual-A
        mma_gemm<false, false, false, false, true><<<dim3(9, 256), 256, SMEM_DUAL>>>(
            NTOK, 3 * D_, D_, ah, al, WH + OFF_QKV, nullptr,
            q, k, v, D_, D_, 3 * D_, nullptr);
        // attention -> ah/al
        attn_kernel<<<B_ * H_, 256, attn_smem>>>(q, k, v, ah, al);
        // x += attn @ Wo + Bo (dual-A: protects residual mainline)
        mma_gemm<true, false, true, false, true><<<dim3(3, 256), 256, SMEM_DUAL>>>(
            NTOK, D_, D_, ah, al, WH + OFF_WO, Bo,
            x, x, x, D_, D_, D_, nullptr);
        // ln2 + split (hi only: W1 is single-A now)
        lnsplit_kernel<false><<<NTOK, 128>>>(x, ln2_s + (size_t)l * D_,
                                             ln2_b + (size_t)l * D_, ah, al);
        // ffn = relu(h @ W1 + B1) -> single fp16 (single-A product)
        mma_gemm<true, true, false, true, false><<<dim3(12, 256), 256, SMEM_SINGLE>>>(
            NTOK, FF_, D_, ah, nullptr, WH + OFF_W1, B1,
            x, x, x, FF_, FF_, FF_, fh);
        // x += ffn @ W2 + B2 (single-A product)
        mma_gemm<true, false, true, false, false><<<dim3(3, 256), 256, SMEM_SINGLE>>>(
            NTOK, D_, FF_, fh, nullptr, WH + OFF_W2, B2,
            x, x, x, D_, D_, D_, nullptr);
    }

    // final layernorm + split (dual: head stays dual-A for output accuracy)
    lnsplit_kernel<true><<<NTOK, 128>>>(x, lnf_s, lnf_b, ah, al);
    mma_gemm<true, false, false, false, true><<<dim3(1, 256), 256, SMEM_DUAL>>>(
        NTOK, 128, D_, ah, al, hwh, head_b,
        out, out, out, 128, V_, V_, nullptr);
}

// round 12
// speedup vs baseline: 1.5325x; 1.1850x over previous
#include <cuda_runtime.h>
#include <cuda_bf16.h>
#include <cuda_fp16.h>
#include <cstdint>

// Problem constants
#define B_    128
#define T_    256
#define D_    384
#define H_    6
#define HD_   64
#define L_    6
#define FF_   1536
#define V_    95
#define NTOK  (B_ * T_)   // 32768

extern __shared__ char dyn_smem[];

// ---------------------------------------------------------------------------
// Baseline-PTX helpers
// ---------------------------------------------------------------------------
__device__ __forceinline__ uint32_t smem_u32(const void* p) {
    uint32_t a;
    asm("{ .reg .u64 t; cvta.to.shared.u64 t, %1; cvt.u32.u64 %0, t; }"
        : "=r"(a) : "l"(p));
    return a;
}
__device__ __forceinline__ void cp16(uint32_t dst, const void* src) {
    asm volatile("cp.async.cg.shared.global [%0], [%1], 16;"
                 :: "r"(dst), "l"(src));
}
#define CP_COMMIT() asm volatile("cp.async.commit_group;" ::: "memory")
#define CP_WAIT0()  asm volatile("cp.async.wait_group 0;" ::: "memory")
#define CP_WAIT1()  asm volatile("cp.async.wait_group 1;" ::: "memory")

// m16n8k16 fp16 MMA, fp32 accumulate
__device__ __forceinline__ void mma16816(float* c, const uint32_t* a,
                                         const uint32_t* b) {
    asm volatile(
        "mma.sync.aligned.m16n8k16.row.col.f32.f16.f16.f32 "
        "{%0,%1,%2,%3},{%4,%5,%6,%7},{%8,%9},{%0,%1,%2,%3};"
        : "+f"(c[0]), "+f"(c[1]), "+f"(c[2]), "+f"(c[3])
        : "r"(a[0]), "r"(a[1]), "r"(a[2]), "r"(a[3]),
          "r"(b[0]), "r"(b[1]));
}
__device__ __forceinline__ void ldsm4(uint32_t& r0, uint32_t& r1,
                                      uint32_t& r2, uint32_t& r3, uint32_t a) {
    asm volatile("ldmatrix.sync.aligned.m8n8.x4.shared.b16 {%0,%1,%2,%3}, [%4];"
                 : "=r"(r0), "=r"(r1), "=r"(r2), "=r"(r3) : "r"(a));
}

// ---------------------------------------------------------------------------
// Weight layout (per layer, packed fp16, transposed [N][K]):
// QKV[3D x D] | WO[D x D] | W1[FF x D] | W2[D x FF]
// ---------------------------------------------------------------------------
#define S_LAYER (4 * D_ * D_ + 2 * D_ * FF_)
#define OFF_QKV 0
#define OFF_WO  (3 * D_ * D_)
#define OFF_W1  (4 * D_ * D_)
#define OFF_W2  (4 * D_ * D_ + FF_ * D_)
#define WTOT    (L_ * S_LAYER)
#define HWPAD   (128 * D_)

__device__ float g_x[NTOK * D_];
__device__ float g_q[NTOK * D_];
__device__ float g_k[NTOK * D_];
__device__ float g_v[NTOK * D_];
__device__ __half g_ah[NTOK * D_],  g_al[NTOK * D_];
__device__ __half g_fh[NTOK * FF_];          // FFN intermediate: single fp16
__device__ __half g_wh[WTOT];
__device__ __half g_hwh[HWPAD];

// ---------------------------------------------------------------------------
// Embedding
// ---------------------------------------------------------------------------
__global__ void embed_kernel(const int* __restrict__ idx,
                             const float* __restrict__ tok,
                             const float* __restrict__ pos,
                             float* __restrict__ x)
{
    int i = blockIdx.x * blockDim.x + threadIdx.x;
    if (i >= NTOK * D_) return;
    int d   = i % D_;
    int row = i / D_;
    int t   = row % T_;
    int tk  = idx[row];
    x[i] = tok[tk * D_ + d] + pos[t * D_ + d];
}

// ---------------------------------------------------------------------------
// Unified weight prep: transpose + fp16 convert, ONE launch.
// Per-layer tiles: qkv 432 | wo 144 | w1 576 | w2 576 -> 1728; +48 head tiles.
// ---------------------------------------------------------------------------
#define TILES_PER_LAYER 1728
#define TILES_WEIGHTS   (L_ * TILES_PER_LAYER)
#define TILES_TOTAL     (TILES_WEIGHTS + 48)

__global__ void prep_kernel(const float* __restrict__ wq,
                            const float* __restrict__ wk,
                            const float* __restrict__ wv,
                            const float* __restrict__ wo,
                            const float* __restrict__ w1,
                            const float* __restrict__ w2,
                            const float* __restrict__ head_w,
                            __half* __restrict__ wh,
                            __half* __restrict__ hwh)
{
    __shared__ float t[32][33];
    int bid = blockIdx.x;
    int tx = threadIdx.x, ty = threadIdx.y;

    const float* W; __half* out;
    int Kd, Nd, n0, k0, nlim;

    if (bid < TILES_WEIGHTS) {
        int layer = bid / TILES_PER_LAYER;
        int r     = bid % TILES_PER_LAYER;
        size_t lw = (size_t)layer * S_LAYER;
        if (r < 432) {                       // wq / wk / wv (144 each)
            int g = r / 144, tt = r % 144;
            W   = (g == 0 ? wq : g == 1 ? wk : wv) + (size_t)layer * D_ * D_;
            out = wh + lw + (size_t)g * D_ * D_;
            Kd = D_; Nd = D_; n0 = (tt % 12) * 32; k0 = (tt / 12) * 32;
        } else if (r < 576) {                // wo (144)
            int tt = r - 432;
            W   = wo + (size_t)layer * D_ * D_;
            out = wh + lw + OFF_WO;
            Kd = D_; Nd = D_; n0 = (tt % 12) * 32; k0 = (tt / 12) * 32;
        } else if (r < 1152) {               // w1 [D x FF] -> [FF x D] (576)
            int tt = r - 576;
            W   = w1 + (size_t)layer * D_ * FF_;
            out = wh + lw + OFF_W1;
            Kd = D_; Nd = FF_; n0 = (tt % 48) * 32; k0 = (tt / 48) * 32;
        } else {                             // w2 [FF x D] -> [D x FF] (576)
            int tt = r - 1152;
            W   = w2 + (size_t)layer * D_ * FF_;
            out = wh + lw + OFF_W2;
            Kd = FF_; Nd = D_; n0 = (tt % 12) * 32; k0 = (tt / 12) * 32;
        }
        nlim = Nd;
    } else {                                 // head: W[D][V] -> [128][D] padded
        int tt = bid - TILES_WEIGHTS;
        W   = head_w;
        out = hwh;
        Kd = D_; Nd = V_; n0 = (tt % 4) * 32; k0 = (tt / 4) * 32;
        nlim = V_;
    }

    for (int r2 = ty; r2 < 32; r2 += 8) {
        int n = n0 + tx;
        t[r2][tx] = (n < nlim) ? W[(size_t)(k0 + r2) * Nd + n] : 0.0f;
    }
    __syncthreads();
    for (int r2 = ty; r2 < 32; r2 += 8) {
        float v = t[tx][r2];
        out[(size_t)(n0 + r2) * Kd + k0 + tx] = __float2half(v);
    }
}

// ---------------------------------------------------------------------------
// Fused LayerNorm + fp16 split; WRITELO controls whether lo-half is stored.
// ---------------------------------------------------------------------------
template<bool WRITELO>
__global__ void __launch_bounds__(128)
lnsplit_kernel(const float* __restrict__ x,
               const float* __restrict__ gam,
               const float* __restrict__ beta,
               __half* __restrict__ hi,
               __half* __restrict__ lo)
{
    int row = blockIdx.x;
    int tid = threadIdx.x;
    const float* xr = x + (size_t)row * D_;

    float v0 = xr[tid];
    float v1 = xr[tid + 128];
    float v2 = xr[tid + 256];

    float s  = v0 + v1 + v2;
    float sq = v0 * v0 + v1 * v1 + v2 * v2;

    #pragma unroll
    for (int off = 16; off > 0; off >>= 1) {
        s  += __shfl_xor_sync(0xffffffffu, s,  off);
        sq += __shfl_xor_sync(0xffffffffu, sq, off);
    }
    __shared__ float ss[4], ssq[4];
    int w = tid >> 5;
    if ((tid & 31) == 0) { ss[w] = s; ssq[w] = sq; }
    __syncthreads();
    s  = ss[0]  + ss[1]  + ss[2]  + ss[3];
    sq = ssq[0] + ssq[1] + ssq[2] + ssq[3];

    const float invn = 1.0f / (float)D_;
    float mean = s * invn;
    float var  = sq * invn - mean * mean;
    float inv  = rsqrtf(var + 1e-5f);

    __half* hp = hi + (size_t)row * D_;
    __half* lp = lo + (size_t)row * D_;
    #pragma unroll
    for (int e = 0; e < 3; e++) {
        int   i2 = tid + e * 128;
        float vv = (e == 0) ? v0 : (e == 1) ? v1 : v2;
        float y  = (vv - mean) * inv * gam[i2] + beta[i2];
        __half h = __float2half(y);
        hp[i2] = h;
        if (WRITELO)
            lp[i2] = __float2half(y - __half2float(h));
    }
}

// ---------------------------------------------------------------------------
// mma.sync GEMM, ldmatrix loads. DUALA: A = Ah+Al (2 products) or Ah only (1).
// 128x128 CTA tile, BK=32, 8 warps (4x2), warp tile 32x64.
// smem rows: 64B data + 16B pad = 80B (conflict-free ldmatrix).
// ---------------------------------------------------------------------------
#define BKG      32
#define ROWB     80
#define TILE_B   (128 * ROWB)      // 10240

template<bool DUALA>
struct GemmSmem { static constexpr int NT = DUALA ? 3 : 2;
                  static constexpr int STAGE = NT * TILE_B;
                  static constexpr int TOTAL = 2 * NT * TILE_B; };

template<bool BIAS, bool RELU, bool RESID, bool SPLITOUT, bool DUALA>
__global__ void __launch_bounds__(256, 2)
mma_gemm(int M, int N, int K,
         const __half* __restrict__ Ah,
         const __half* __restrict__ Al,
         const __half* __restrict__ Bh,   // [N,K]
         const float* __restrict__ bias,
         float* __restrict__ C0, float* __restrict__ C1, float* __restrict__ C2,
         int nsplit, int ldc, int nmax,
         __half* __restrict__ oh)
{
    constexpr int NT      = GemmSmem<DUALA>::NT;
    constexpr int STAGE_B = GemmSmem<DUALA>::STAGE;

    char* smem = dyn_smem;
    const uint32_t sb = smem_u32(smem);

    const int tid  = threadIdx.x;
    const int wid  = tid >> 5;
    const int lane = tid & 31;
    const int wm   = wid & 3;
    const int wn   = wid >> 2;
    const int g    = lane >> 2;
    const int t    = lane & 3;

    const int n0 = blockIdx.x * 128;
    const int m0 = blockIdx.y * 128;

    const __half* gsrc[3];
    gsrc[0] = Ah + (size_t)m0 * K;
    gsrc[1] = DUALA ? (Al + (size_t)m0 * K) : (Bh + (size_t)n0 * K);
    gsrc[2] = Bh + (size_t)n0 * K;   // only used when DUALA

    const int KT = K / BKG;

    auto load_stage = [&](int kt, int s) {
        const uint32_t sdst = sb + s * STAGE_B;
        const int kc = kt * BKG;
        #pragma unroll
        for (int tile = 0; tile < NT; tile++) {
            const __half* gp = gsrc[tile];
            int row = tid >> 1, ch = tid & 1;
            cp16(sdst + tile * TILE_B + row * ROWB + ch * 16,
                 gp + (size_t)row * K + kc + ch * 8);
            cp16(sdst + tile * TILE_B + row * ROWB + (ch + 2) * 16,
                 gp + (size_t)row * K + kc + (ch + 2) * 8);
        }
    };

    float acc[2][8][4];
    #pragma unroll
    for (int i = 0; i < 2; i++)
        #pragma unroll
        for (int j = 0; j < 8; j++)
            #pragma unroll
            for (int c = 0; c < 4; c++) acc[i][j][c] = 0.0f;

    const uint32_t aOff = (uint32_t)((wm * 32 + (lane & 15)) * ROWB +
                                     ((lane >> 4) & 1) * 16);
    const uint32_t bOff = (uint32_t)((wn * 64 + (lane & 7) +
                                      ((lane >> 4) & 1) * 8) * ROWB +
                                     ((lane >> 3) & 1) * 16);

    load_stage(0, 0);
    CP_COMMIT();

    for (int kt = 0; kt < KT; kt++) {
        const int s = kt & 1;
        if (kt + 1 < KT) {
            load_stage(kt + 1, s ^ 1);
            CP_COMMIT();
            CP_WAIT1();
        } else {
            CP_WAIT0();
        }
        __syncthreads();

        const uint32_t base   = sb + s * STAGE_B;
        const uint32_t aBaseH = base + aOff;
        const uint32_t aBaseL = base + TILE_B + aOff;          // DUALA only
        const uint32_t bBaseH = base + (NT - 1) * TILE_B + bOff;

        #pragma unroll
        for (int ks = 0; ks < 2; ks++) {
            uint32_t ah[2][4], al[2][4];
            #pragma unroll
            for (int i = 0; i < 2; i++) {
                ldsm4(ah[i][0], ah[i][1], ah[i][2], ah[i][3],
                      aBaseH + i * (16 * ROWB) + ks * 32);
                if (DUALA)
                    ldsm4(al[i][0], al[i][1], al[i][2], al[i][3],
                          aBaseL + i * (16 * ROWB) + ks * 32);
            }
            #pragma unroll
            for (int half = 0; half < 2; half++) {
                uint32_t bhr[8];
                ldsm4(bhr[0], bhr[1], bhr[2], bhr[3],
                      bBaseH + (half * 32) * ROWB + ks * 32);
                ldsm4(bhr[4], bhr[5], bhr[6], bhr[7],
                      bBaseH + (half * 32 + 16) * ROWB + ks * 32);
                #pragma unroll
                for (int i = 0; i < 2; i++)
                    #pragma unroll
                    for (int j4 = 0; j4 < 4; j4++)
                        mma16816(acc[i][half * 4 + j4], ah[i], &bhr[2 * j4]);
                if (DUALA) {
                    #pragma unroll
                    for (int i = 0; i < 2; i++)
                        #pragma unroll
                        for (int j4 = 0; j4 < 4; j4++)
                            mma16816(acc[i][half * 4 + j4], al[i], &bhr[2 * j4]);
                }
            }
        }
        __syncthreads();
    }

    // ---- epilogue ----
    const int which = n0 / nsplit;
    const int ncol0 = n0 - which * nsplit;
    float* Cb = (which == 0) ? C0 : (which == 1) ? C1 : C2;

    #pragma unroll
    for (int i = 0; i < 2; i++) {
        const int rm = m0 + wm * 32 + i * 16 + g;
        #pragma unroll
        for (int j = 0; j < 8; j++) {
            const int cnl = ncol0 + wn * 64 + j * 8 + 2 * t;
            const int gn  = n0    + wn * 64 + j * 8 + 2 * t;
            float v00 = acc[i][j][0], v01 = acc[i][j][1];
            float v10 = acc[i][j][2], v11 = acc[i][j][3];
            if (BIAS) {
                float b0 = (gn     < nmax) ? bias[gn]     : 0.0f;
                float b1 = (gn + 1 < nmax) ? bias[gn + 1] : 0.0f;
                v00 += b0; v01 += b1; v10 += b0; v11 += b1;
            }
            if (RELU) {
                v00 = fmaxf(v00, 0.f); v01 = fmaxf(v01, 0.f);
                v10 = fmaxf(v10, 0.f); v11 = fmaxf(v11, 0.f);
            }
            if (SPLITOUT) {
                size_t p0 = (size_t)rm * ldc + cnl;
                size_t p1 = (size_t)(rm + 8) * ldc + cnl;
                *reinterpret_cast<__half2*>(oh + p0) =
                    __half2{__float2half(v00), __float2half(v01)};
                *reinterpret_cast<__half2*>(oh + p1) =
                    __half2{__float2half(v10), __float2half(v11)};
            } else if (nmax == N) {
                float* p0 = Cb + (size_t)rm * ldc + cnl;
                float* p1 = Cb + (size_t)(rm + 8) * ldc + cnl;
                float2 w0 = make_float2(v00, v01);
                float2 w1 = make_float2(v10, v11);
                if (RESID) {
                    float2 o0 = *reinterpret_cast<const float2*>(p0);
                    float2 o1 = *reinterpret_cast<const float2*>(p1);
                    w0.x += o0.x; w0.y += o0.y;
                    w1.x += o1.x; w1.y += o1.y;
                }
                *reinterpret_cast<float2*>(p0) = w0;
                *reinterpret_cast<float2*>(p1) = w1;
            } else {
                if (gn < nmax) {
                    Cb[(size_t)rm * ldc + cnl]       = v00;
                    Cb[(size_t)(rm + 8) * ldc + cnl] = v10;
                }
                if (gn + 1 < nmax) {
                    Cb[(size_t)rm * ldc + cnl + 1]       = v01;
                    Cb[(size_t)(rm + 8) * ldc + cnl + 1] = v11;
                }
            }
        }
    }
}

// ---------------------------------------------------------------------------
// Causal attention; output written as fp16 hi only (WO is single-A)
// ---------------------------------------------------------------------------
__global__ void __launch_bounds__(256)
attn_kernel(const float* __restrict__ q,
            const float* __restrict__ k,
            const float* __restrict__ v,
            __half* __restrict__ oh)
{
    float* smem = reinterpret_cast<float*>(dyn_smem);
    float* ks = smem;
    float* vs = smem + T_ * HD_;

    int bh = blockIdx.x;
    int b  = bh / H_;
    int h  = bh % H_;
    int tid = threadIdx.x;

    const size_t base = (size_t)(b * T_) * D_ + h * HD_;

    const float4* krow = reinterpret_cast<const float4*>(k + base + (size_t)tid * D_);
    const float4* vrow = reinterpret_cast<const float4*>(v + base + (size_t)tid * D_);
    float4* ksd = reinterpret_cast<float4*>(ks + tid * HD_);
    float4* vsd = reinterpret_cast<float4*>(vs + tid * HD_);
    #pragma unroll
    for (int d4 = 0; d4 < HD_ / 4; d4++) {
        ksd[d4] = krow[d4];
        vsd[d4] = vrow[d4];
    }
    __syncthreads();

    float qr[HD_];
    const float4* qrow = reinterpret_cast<const float4*>(q + base + (size_t)tid * D_);
    #pragma unroll
    for (int d4 = 0; d4 < HD_ / 4; d4++) {
        float4 tv = qrow[d4];
        qr[d4 * 4 + 0] = tv.x; qr[d4 * 4 + 1] = tv.y;
        qr[d4 * 4 + 2] = tv.z; qr[d4 * 4 + 3] = tv.w;
    }

    float m = -1e30f, l = 0.0f;
    float o[HD_];
    #pragma unroll
    for (int d = 0; d < HD_; d++) o[d] = 0.0f;

    const float scale = 0.125f;

    for (int j = 0; j <= tid; j++) {
        const float* kj = ks + j * HD_;
        float s0 = 0.f, s1 = 0.f, s2 = 0.f, s3 = 0.f;
        #pragma unroll
        for (int d = 0; d < HD_; d += 4) {
            s0 = fmaf(qr[d],     kj[d],     s0);
            s1 = fmaf(qr[d + 1], kj[d + 1], s1);
            s2 = fmaf(qr[d + 2], kj[d + 2], s2);
            s3 = fmaf(qr[d + 3], kj[d + 3], s3);
        }
        float s = ((s0 + s1) + (s2 + s3)) * scale;

        if (s > m) {
            float corr = __expf(m - s);
            l *= corr;
            #pragma unroll
            for (int d = 0; d < HD_; d++) o[d] *= corr;
            m = s;
        }
        float p = __expf(s - m);
        l += p;
        const float* vj = vs + j * HD_;
        #pragma unroll
        for (int d = 0; d < HD_; d++) o[d] = fmaf(p, vj[d], o[d]);
    }

    float invl = 1.0f / l;
    __half* hp = oh + base + (size_t)tid * D_;
    #pragma unroll
    for (int d = 0; d < HD_; d++)
        hp[d] = __float2half(o[d] * invl);
}

// ---------------------------------------------------------------------------
// Host launcher
// ---------------------------------------------------------------------------
extern "C" void kernel_launch(void* const* d_in, const int* in_sizes, int n_in,
                              void* d_out, int out_size)
{
    const int*   idx    = (const int*)  d_in[0];
    const float* tok    = (const float*)d_in[1];
    const float* pos    = (const float*)d_in[2];
    const float* ln1_s  = (const float*)d_in[3];
    const float* ln1_b  = (const float*)d_in[4];
    const float* wq     = (const float*)d_in[5];
    const float* wk     = (const float*)d_in[6];
    const float* wv     = (const float*)d_in[7];
    const float* wo     = (const float*)d_in[8];
    const float* bo     = (const float*)d_in[9];
    const float* ln2_s  = (const float*)d_in[10];
    const float* ln2_b  = (const float*)d_in[11];
    const float* w1     = (const float*)d_in[12];
    const float* b1     = (const float*)d_in[13];
    const float* w2     = (const float*)d_in[14];
    const float* b2     = (const float*)d_in[15];
    const float* lnf_s  = (const float*)d_in[16];
    const float* lnf_b  = (const float*)d_in[17];
    const float* head_w = (const float*)d_in[18];
    const float* head_b = (const float*)d_in[19];
    float* out = (float*)d_out;

    float *x, *q, *k, *v;
    __half *ah, *al, *fh, *wh, *hwh;
    cudaGetSymbolAddress((void**)&x,   g_x);
    cudaGetSymbolAddress((void**)&q,   g_q);
    cudaGetSymbolAddress((void**)&k,   g_k);
    cudaGetSymbolAddress((void**)&v,   g_v);
    cudaGetSymbolAddress((void**)&ah,  g_ah);
    cudaGetSymbolAddress((void**)&al,  g_al);
    cudaGetSymbolAddress((void**)&fh,  g_fh);
    cudaGetSymbolAddress((void**)&wh,  g_wh);
    cudaGetSymbolAddress((void**)&hwh, g_hwh);

    const int SMEM_DUAL   = GemmSmem<true>::TOTAL;    // 61440
    const int SMEM_SINGLE = GemmSmem<false>::TOTAL;   // 40960

    cudaFuncSetAttribute(attn_kernel,
                         cudaFuncAttributeMaxDynamicSharedMemorySize,
                         2 * T_ * HD_ * (int)sizeof(float));
    cudaFuncSetAttribute((const void*)mma_gemm<false, false, false, false, false>,
                         cudaFuncAttributeMaxDynamicSharedMemorySize, SMEM_SINGLE);
    cudaFuncSetAttribute((const void*)mma_gemm<true, false, true, false, false>,
                         cudaFuncAttributeMaxDynamicSharedMemorySize, SMEM_SINGLE);
    cudaFuncSetAttribute((const void*)mma_gemm<true, true, false, true, false>,
                         cudaFuncAttributeMaxDynamicSharedMemorySize, SMEM_SINGLE);
    cudaFuncSetAttribute((const void*)mma_gemm<true, false, false, false, true>,
                         cudaFuncAttributeMaxDynamicSharedMemorySize, SMEM_DUAL);

    // [0] one-launch weight prep
    prep_kernel<<<TILES_TOTAL, dim3(32, 8)>>>(wq, wk, wv, wo, w1, w2, head_w,
                                              wh, hwh);
    // [1] embedding
    embed_kernel<<<(NTOK * D_ + 255) / 256, 256>>>(idx, tok, pos, x);

    const int attn_smem = 2 * T_ * HD_ * (int)sizeof(float);

    for (int l = 0; l < L_; l++) {
        const __half* WH = wh + (size_t)l * S_LAYER;
        const float* Bo = bo + (size_t)l * D_;
        const float* B1 = b1 + (size_t)l * FF_;
        const float* B2 = b2 + (size_t)l * D_;

        // ln1 + split (hi only: QKV single-A)
        lnsplit_kernel<false><<<NTOK, 128>>>(x, ln1_s + (size_t)l * D_,
                                             ln1_b + (size_t)l * D_, ah, al);
        // fused QKV (N=1152), single-A
        mma_gemm<false, false, false, false, false><<<dim3(9, 256), 256, SMEM_SINGLE>>>(
            NTOK, 3 * D_, D_, ah, nullptr, WH + OFF_QKV, nullptr,
            q, k, v, D_, D_, 3 * D_, nullptr);
        // attention -> ah (hi only)
        attn_kernel<<<B_ * H_, 256, attn_smem>>>(q, k, v, ah);
        // x += attn @ Wo + Bo (single-A)
        mma_gemm<true, false, true, false, false><<<dim3(3, 256), 256, SMEM_SINGLE>>>(
            NTOK, D_, D_, ah, nullptr, WH + OFF_WO, Bo,
            x, x, x, D_, D_, D_, nullptr);
        // ln2 + split (hi only: W1 single-A)
        lnsplit_kernel<false><<<NTOK, 128>>>(x, ln2_s + (size_t)l * D_,
                                             ln2_b + (size_t)l * D_, ah, al);
        // ffn = relu(h @ W1 + B1) -> single fp16 (single-A)
        mma_gemm<true, true, false, true, false><<<dim3(12, 256), 256, SMEM_SINGLE>>>(
            NTOK, FF_, D_, ah, nullptr, WH + OFF_W1, B1,
            x, x, x, FF_, FF_, FF_, fh);
        // x += ffn @ W2 + B2 (single-A)
        mma_gemm<true, false, true, false, false><<<dim3(3, 256), 256, SMEM_SINGLE>>>(
            NTOK, D_, FF_, fh, nullptr, WH + OFF_W2, B2,
            x, x, x, D_, D_, D_, nullptr);
    }

    // final layernorm + split (dual: head stays dual-A for output accuracy)
    lnsplit_kernel<true><<<NTOK, 128>>>(x, lnf_s, lnf_b, ah, al);
    mma_gemm<true, false, false, false, true><<<dim3(1, 256), 256, SMEM_DUAL>>>(
        NTOK, 128, D_, ah, al, hwh, head_b,
        out, out, out, 128, V_, V_, nullptr);
}

// round 13
// speedup vs baseline: 1.5858x; 1.0348x over previous
#include <cuda_runtime.h>
#include <cuda_bf16.h>
#include <cuda_fp16.h>
#include <cstdint>

// Problem constants
#define B_    128
#define T_    256
#define D_    384
#define H_    6
#define HD_   64
#define L_    6
#define FF_   1536
#define V_    95
#define NTOK  (B_ * T_)   // 32768

extern __shared__ char dyn_smem[];

// ---------------------------------------------------------------------------
// Baseline-PTX helpers
// ---------------------------------------------------------------------------
__device__ __forceinline__ uint32_t smem_u32(const void* p) {
    uint32_t a;
    asm("{ .reg .u64 t; cvta.to.shared.u64 t, %1; cvt.u32.u64 %0, t; }"
        : "=r"(a) : "l"(p));
    return a;
}
__device__ __forceinline__ void cp16(uint32_t dst, const void* src) {
    asm volatile("cp.async.cg.shared.global [%0], [%1], 16;"
                 :: "r"(dst), "l"(src));
}
#define CP_COMMIT() asm volatile("cp.async.commit_group;" ::: "memory")
#define CP_WAIT0()  asm volatile("cp.async.wait_group 0;" ::: "memory")
#define CP_WAIT1()  asm volatile("cp.async.wait_group 1;" ::: "memory")

// m16n8k16 fp16 MMA, fp32 accumulate
__device__ __forceinline__ void mma16816(float* c, const uint32_t* a,
                                         const uint32_t* b) {
    asm volatile(
        "mma.sync.aligned.m16n8k16.row.col.f32.f16.f16.f32 "
        "{%0,%1,%2,%3},{%4,%5,%6,%7},{%8,%9},{%0,%1,%2,%3};"
        : "+f"(c[0]), "+f"(c[1]), "+f"(c[2]), "+f"(c[3])
        : "r"(a[0]), "r"(a[1]), "r"(a[2]), "r"(a[3]),
          "r"(b[0]), "r"(b[1]));
}
__device__ __forceinline__ void ldsm4(uint32_t& r0, uint32_t& r1,
                                      uint32_t& r2, uint32_t& r3, uint32_t a) {
    asm volatile("ldmatrix.sync.aligned.m8n8.x4.shared.b16 {%0,%1,%2,%3}, [%4];"
                 : "=r"(r0), "=r"(r1), "=r"(r2), "=r"(r3) : "r"(a));
}

// ---------------------------------------------------------------------------
// Weight layout (per layer, packed fp16, transposed [N][K]):
// QKV[3D x D] | WO[D x D] | W1[FF x D] | W2[D x FF]
// ---------------------------------------------------------------------------
#define S_LAYER (4 * D_ * D_ + 2 * D_ * FF_)
#define OFF_QKV 0
#define OFF_WO  (3 * D_ * D_)
#define OFF_W1  (4 * D_ * D_)
#define OFF_W2  (4 * D_ * D_ + FF_ * D_)
#define WTOT    (L_ * S_LAYER)
#define HWPAD   (128 * D_)

__device__ float g_x[NTOK * D_];
__device__ float g_q[NTOK * D_];
__device__ float g_k[NTOK * D_];
__device__ float g_v[NTOK * D_];
__device__ __half g_ah[NTOK * D_],  g_al[NTOK * D_];
__device__ __half g_fh[NTOK * FF_];          // FFN intermediate: single fp16
__device__ __half g_wh[WTOT];
__device__ __half g_hwh[HWPAD];

// ---------------------------------------------------------------------------
// Embedding
// ---------------------------------------------------------------------------
__global__ void embed_kernel(const int* __restrict__ idx,
                             const float* __restrict__ tok,
                             const float* __restrict__ pos,
                             float* __restrict__ x)
{
    int i = blockIdx.x * blockDim.x + threadIdx.x;
    if (i >= NTOK * D_) return;
    int d   = i % D_;
    int row = i / D_;
    int t   = row % T_;
    int tk  = idx[row];
    x[i] = tok[tk * D_ + d] + pos[t * D_ + d];
}

// ---------------------------------------------------------------------------
// Unified weight prep: transpose + fp16 convert, ONE launch.
// Per-layer tiles: qkv 432 | wo 144 | w1 576 | w2 576 -> 1728; +48 head tiles.
// ---------------------------------------------------------------------------
#define TILES_PER_LAYER 1728
#define TILES_WEIGHTS   (L_ * TILES_PER_LAYER)
#define TILES_TOTAL     (TILES_WEIGHTS + 48)

__global__ void prep_kernel(const float* __restrict__ wq,
                            const float* __restrict__ wk,
                            const float* __restrict__ wv,
                            const float* __restrict__ wo,
                            const float* __restrict__ w1,
                            const float* __restrict__ w2,
                            const float* __restrict__ head_w,
                            __half* __restrict__ wh,
                            __half* __restrict__ hwh)
{
    __shared__ float t[32][33];
    int bid = blockIdx.x;
    int tx = threadIdx.x, ty = threadIdx.y;

    const float* W; __half* out;
    int Kd, Nd, n0, k0, nlim;

    if (bid < TILES_WEIGHTS) {
        int layer = bid / TILES_PER_LAYER;
        int r     = bid % TILES_PER_LAYER;
        size_t lw = (size_t)layer * S_LAYER;
        if (r < 432) {                       // wq / wk / wv (144 each)
            int g = r / 144, tt = r % 144;
            W   = (g == 0 ? wq : g == 1 ? wk : wv) + (size_t)layer * D_ * D_;
            out = wh + lw + (size_t)g * D_ * D_;
            Kd = D_; Nd = D_; n0 = (tt % 12) * 32; k0 = (tt / 12) * 32;
        } else if (r < 576) {                // wo (144)
            int tt = r - 432;
            W   = wo + (size_t)layer * D_ * D_;
            out = wh + lw + OFF_WO;
            Kd = D_; Nd = D_; n0 = (tt % 12) * 32; k0 = (tt / 12) * 32;
        } else if (r < 1152) {               // w1 [D x FF] -> [FF x D] (576)
            int tt = r - 576;
            W   = w1 + (size_t)layer * D_ * FF_;
            out = wh + lw + OFF_W1;
            Kd = D_; Nd = FF_; n0 = (tt % 48) * 32; k0 = (tt / 48) * 32;
        } else {                             // w2 [FF x D] -> [D x FF] (576)
            int tt = r - 1152;
            W   = w2 + (size_t)layer * D_ * FF_;
            out = wh + lw + OFF_W2;
            Kd = FF_; Nd = D_; n0 = (tt % 12) * 32; k0 = (tt / 12) * 32;
        }
        nlim = Nd;
    } else {                                 // head: W[D][V] -> [128][D] padded
        int tt = bid - TILES_WEIGHTS;
        W   = head_w;
        out = hwh;
        Kd = D_; Nd = V_; n0 = (tt % 4) * 32; k0 = (tt / 4) * 32;
        nlim = V_;
    }

    for (int r2 = ty; r2 < 32; r2 += 8) {
        int n = n0 + tx;
        t[r2][tx] = (n < nlim) ? W[(size_t)(k0 + r2) * Nd + n] : 0.0f;
    }
    __syncthreads();
    for (int r2 = ty; r2 < 32; r2 += 8) {
        float v = t[tx][r2];
        out[(size_t)(n0 + r2) * Kd + k0 + tx] = __float2half(v);
    }
}

// ---------------------------------------------------------------------------
// Fused LayerNorm + fp16 split; WRITELO controls whether lo-half is stored.
// ---------------------------------------------------------------------------
template<bool WRITELO>
__global__ void __launch_bounds__(128)
lnsplit_kernel(const float* __restrict__ x,
               const float* __restrict__ gam,
               const float* __restrict__ beta,
               __half* __restrict__ hi,
               __half* __restrict__ lo)
{
    int row = blockIdx.x;
    int tid = threadIdx.x;
    const float* xr = x + (size_t)row * D_;

    float v0 = xr[tid];
    float v1 = xr[tid + 128];
    float v2 = xr[tid + 256];

    float s  = v0 + v1 + v2;
    float sq = v0 * v0 + v1 * v1 + v2 * v2;

    #pragma unroll
    for (int off = 16; off > 0; off >>= 1) {
        s  += __shfl_xor_sync(0xffffffffu, s,  off);
        sq += __shfl_xor_sync(0xffffffffu, sq, off);
    }
    __shared__ float ss[4], ssq[4];
    int w = tid >> 5;
    if ((tid & 31) == 0) { ss[w] = s; ssq[w] = sq; }
    __syncthreads();
    s  = ss[0]  + ss[1]  + ss[2]  + ss[3];
    sq = ssq[0] + ssq[1] + ssq[2] + ssq[3];

    const float invn = 1.0f / (float)D_;
    float mean = s * invn;
    float var  = sq * invn - mean * mean;
    float inv  = rsqrtf(var + 1e-5f);

    __half* hp = hi + (size_t)row * D_;
    __half* lp = lo + (size_t)row * D_;
    #pragma unroll
    for (int e = 0; e < 3; e++) {
        int   i2 = tid + e * 128;
        float vv = (e == 0) ? v0 : (e == 1) ? v1 : v2;
        float y  = (vv - mean) * inv * gam[i2] + beta[i2];
        __half h = __float2half(y);
        hp[i2] = h;
        if (WRITELO)
            lp[i2] = __float2half(y - __half2float(h));
    }
}

// ---------------------------------------------------------------------------
// mma.sync GEMM, ldmatrix loads. DUALA: A = Ah+Al (2 products) or Ah only (1).
// 128x128 CTA tile, BK=32, 8 warps (4x2), warp tile 32x64.
// smem rows: 64B data + 16B pad = 80B (conflict-free ldmatrix).
// ---------------------------------------------------------------------------
#define BKG      32
#define ROWB     80
#define TILE_B   (128 * ROWB)      // 10240

template<bool DUALA>
struct GemmSmem { static constexpr int NT = DUALA ? 3 : 2;
                  static constexpr int STAGE = NT * TILE_B;
                  static constexpr int TOTAL = 2 * NT * TILE_B; };

template<bool BIAS, bool RELU, bool RESID, bool SPLITOUT, bool DUALA>
__global__ void __launch_bounds__(256, 2)
mma_gemm(int M, int N, int K,
         const __half* __restrict__ Ah,
         const __half* __restrict__ Al,
         const __half* __restrict__ Bh,   // [N,K]
         const float* __restrict__ bias,
         float* __restrict__ C0, float* __restrict__ C1, float* __restrict__ C2,
         int nsplit, int ldc, int nmax,
         __half* __restrict__ oh)
{
    constexpr int NT      = GemmSmem<DUALA>::NT;
    constexpr int STAGE_B = GemmSmem<DUALA>::STAGE;

    char* smem = dyn_smem;
    const uint32_t sb = smem_u32(smem);

    const int tid  = threadIdx.x;
    const int wid  = tid >> 5;
    const int lane = tid & 31;
    const int wm   = wid & 3;
    const int wn   = wid >> 2;
    const int g    = lane >> 2;
    const int t    = lane & 3;

    const int n0 = blockIdx.x * 128;
    const int m0 = blockIdx.y * 128;

    const __half* gsrc[3];
    gsrc[0] = Ah + (size_t)m0 * K;
    gsrc[1] = DUALA ? (Al + (size_t)m0 * K) : (Bh + (size_t)n0 * K);
    gsrc[2] = Bh + (size_t)n0 * K;   // only used when DUALA

    const int KT = K / BKG;

    auto load_stage = [&](int kt, int s) {
        const uint32_t sdst = sb + s * STAGE_B;
        const int kc = kt * BKG;
        #pragma unroll
        for (int tile = 0; tile < NT; tile++) {
            const __half* gp = gsrc[tile];
            int row = tid >> 1, ch = tid & 1;
            cp16(sdst + tile * TILE_B + row * ROWB + ch * 16,
                 gp + (size_t)row * K + kc + ch * 8);
            cp16(sdst + tile * TILE_B + row * ROWB + (ch + 2) * 16,
                 gp + (size_t)row * K + kc + (ch + 2) * 8);
        }
    };

    float acc[2][8][4];
    #pragma unroll
    for (int i = 0; i < 2; i++)
        #pragma unroll
        for (int j = 0; j < 8; j++)
            #pragma unroll
            for (int c = 0; c < 4; c++) acc[i][j][c] = 0.0f;

    const uint32_t aOff = (uint32_t)((wm * 32 + (lane & 15)) * ROWB +
                                     ((lane >> 4) & 1) * 16);
    const uint32_t bOff = (uint32_t)((wn * 64 + (lane & 7) +
                                      ((lane >> 4) & 1) * 8) * ROWB +
                                     ((lane >> 3) & 1) * 16);

    load_stage(0, 0);
    CP_COMMIT();

    for (int kt = 0; kt < KT; kt++) {
        const int s = kt & 1;
        if (kt + 1 < KT) {
            load_stage(kt + 1, s ^ 1);
            CP_COMMIT();
            CP_WAIT1();
        } else {
            CP_WAIT0();
        }
        __syncthreads();

        const uint32_t base   = sb + s * STAGE_B;
        const uint32_t aBaseH = base + aOff;
        const uint32_t aBaseL = base + TILE_B + aOff;          // DUALA only
        const uint32_t bBaseH = base + (NT - 1) * TILE_B + bOff;

        #pragma unroll
        for (int ks = 0; ks < 2; ks++) {
            uint32_t ah[2][4], al[2][4];
            #pragma unroll
            for (int i = 0; i < 2; i++) {
                ldsm4(ah[i][0], ah[i][1], ah[i][2], ah[i][3],
                      aBaseH + i * (16 * ROWB) + ks * 32);
                if (DUALA)
                    ldsm4(al[i][0], al[i][1], al[i][2], al[i][3],
                          aBaseL + i * (16 * ROWB) + ks * 32);
            }
            #pragma unroll
            for (int half = 0; half < 2; half++) {
                uint32_t bhr[8];
                ldsm4(bhr[0], bhr[1], bhr[2], bhr[3],
                      bBaseH + (half * 32) * ROWB + ks * 32);
                ldsm4(bhr[4], bhr[5], bhr[6], bhr[7],
                      bBaseH + (half * 32 + 16) * ROWB + ks * 32);
                #pragma unroll
                for (int i = 0; i < 2; i++)
                    #pragma unroll
                    for (int j4 = 0; j4 < 4; j4++)
                        mma16816(acc[i][half * 4 + j4], ah[i], &bhr[2 * j4]);
                if (DUALA) {
                    #pragma unroll
                    for (int i = 0; i < 2; i++)
                        #pragma unroll
                        for (int j4 = 0; j4 < 4; j4++)
                            mma16816(acc[i][half * 4 + j4], al[i], &bhr[2 * j4]);
                }
            }
        }
        __syncthreads();
    }

    // ---- epilogue ----
    const int which = n0 / nsplit;
    const int ncol0 = n0 - which * nsplit;
    float* Cb = (which == 0) ? C0 : (which == 1) ? C1 : C2;

    #pragma unroll
    for (int i = 0; i < 2; i++) {
        const int rm = m0 + wm * 32 + i * 16 + g;
        #pragma unroll
        for (int j = 0; j < 8; j++) {
            const int cnl = ncol0 + wn * 64 + j * 8 + 2 * t;
            const int gn  = n0    + wn * 64 + j * 8 + 2 * t;
            float v00 = acc[i][j][0], v01 = acc[i][j][1];
            float v10 = acc[i][j][2], v11 = acc[i][j][3];
            if (BIAS) {
                float b0 = (gn     < nmax) ? bias[gn]     : 0.0f;
                float b1 = (gn + 1 < nmax) ? bias[gn + 1] : 0.0f;
                v00 += b0; v01 += b1; v10 += b0; v11 += b1;
            }
            if (RELU) {
                v00 = fmaxf(v00, 0.f); v01 = fmaxf(v01, 0.f);
                v10 = fmaxf(v10, 0.f); v11 = fmaxf(v11, 0.f);
            }
            if (SPLITOUT) {
                size_t p0 = (size_t)rm * ldc + cnl;
                size_t p1 = (size_t)(rm + 8) * ldc + cnl;
                *reinterpret_cast<__half2*>(oh + p0) =
                    __half2{__float2half(v00), __float2half(v01)};
                *reinterpret_cast<__half2*>(oh + p1) =
                    __half2{__float2half(v10), __float2half(v11)};
            } else if (nmax == N) {
                float* p0 = Cb + (size_t)rm * ldc + cnl;
                float* p1 = Cb + (size_t)(rm + 8) * ldc + cnl;
                float2 w0 = make_float2(v00, v01);
                float2 w1 = make_float2(v10, v11);
                if (RESID) {
                    float2 o0 = *reinterpret_cast<const float2*>(p0);
                    float2 o1 = *reinterpret_cast<const float2*>(p1);
                    w0.x += o0.x; w0.y += o0.y;
                    w1.x += o1.x; w1.y += o1.y;
                }
                *reinterpret_cast<float2*>(p0) = w0;
                *reinterpret_cast<float2*>(p1) = w1;
            } else {
                if (gn < nmax) {
                    Cb[(size_t)rm * ldc + cnl]       = v00;
                    Cb[(size_t)(rm + 8) * ldc + cnl] = v10;
                }
                if (gn + 1 < nmax) {
                    Cb[(size_t)rm * ldc + cnl + 1]       = v01;
                    Cb[(size_t)(rm + 8) * ldc + cnl + 1] = v11;
                }
            }
        }
    }
}

// ---------------------------------------------------------------------------
// Causal attention v2: 2 CTAs per (b,h), 128 threads each, keys streamed in
// 128-row chunks through 64KB smem -> 3 CTAs/SM co-resident.
// Thread handles query row = half*128 + tid; j visits keys in the same
// ascending order as before (bitwise-identical results).
// ---------------------------------------------------------------------------
#define KCH 128
__global__ void __launch_bounds__(128)
attn_kernel(const float* __restrict__ q,
            const float* __restrict__ k,
            const float* __restrict__ v,
            __half* __restrict__ oh)
{
    float* smem = reinterpret_cast<float*>(dyn_smem);
    float* ks = smem;                 // [KCH][HD_]
    float* vs = smem + KCH * HD_;     // [KCH][HD_]

    const int cta  = blockIdx.x;
    const int bh   = cta >> 1;
    const int half = cta & 1;
    const int b    = bh / H_;
    const int h    = bh % H_;
    const int tid  = threadIdx.x;
    const int row  = half * KCH + tid;

    const size_t base = (size_t)(b * T_) * D_ + h * HD_;

    float qr[HD_];
    const float4* qrow = reinterpret_cast<const float4*>(q + base + (size_t)row * D_);
    #pragma unroll
    for (int d4 = 0; d4 < HD_ / 4; d4++) {
        float4 tv = qrow[d4];
        qr[d4 * 4 + 0] = tv.x; qr[d4 * 4 + 1] = tv.y;
        qr[d4 * 4 + 2] = tv.z; qr[d4 * 4 + 3] = tv.w;
    }

    float m = -1e30f, l = 0.0f;
    float o[HD_];
    #pragma unroll
    for (int d = 0; d < HD_; d++) o[d] = 0.0f;

    const float scale = 0.125f;

    for (int c = 0; c <= half; c++) {
        __syncthreads();   // protect previous chunk's consumers before overwrite
        {
            const int krow = c * KCH + tid;
            const float4* kr = reinterpret_cast<const float4*>(k + base + (size_t)krow * D_);
            const float4* vr = reinterpret_cast<const float4*>(v + base + (size_t)krow * D_);
            float4* ksd = reinterpret_cast<float4*>(ks + tid * HD_);
            float4* vsd = reinterpret_cast<float4*>(vs + tid * HD_);
            #pragma unroll
            for (int d4 = 0; d4 < HD_ / 4; d4++) {
                ksd[d4] = kr[d4];
                vsd[d4] = vr[d4];
            }
        }
        __syncthreads();

        const int jend = (c == half) ? tid : (KCH - 1);
        for (int jl = 0; jl <= jend; jl++) {
            const float* kj = ks + jl * HD_;
            float s0 = 0.f, s1 = 0.f, s2 = 0.f, s3 = 0.f;
            #pragma unroll
            for (int d = 0; d < HD_; d += 4) {
                s0 = fmaf(qr[d],     kj[d],     s0);
                s1 = fmaf(qr[d + 1], kj[d + 1], s1);
                s2 = fmaf(qr[d + 2], kj[d + 2], s2);
                s3 = fmaf(qr[d + 3], kj[d + 3], s3);
            }
            float s = ((s0 + s1) + (s2 + s3)) * scale;

            if (s > m) {
                float corr = __expf(m - s);
                l *= corr;
                #pragma unroll
                for (int d = 0; d < HD_; d++) o[d] *= corr;
                m = s;
            }
            float p = __expf(s - m);
            l += p;
            const float* vj = vs + jl * HD_;
            #pragma unroll
            for (int d = 0; d < HD_; d++) o[d] = fmaf(p, vj[d], o[d]);
        }
    }

    float invl = 1.0f / l;
    __half* hp = oh + base + (size_t)row * D_;
    #pragma unroll
    for (int d = 0; d < HD_; d++)
        hp[d] = __float2half(o[d] * invl);
}

// ---------------------------------------------------------------------------
// Host launcher
// ---------------------------------------------------------------------------
extern "C" void kernel_launch(void* const* d_in, const int* in_sizes, int n_in,
                              void* d_out, int out_size)
{
    const int*   idx    = (const int*)  d_in[0];
    const float* tok    = (const float*)d_in[1];
    const float* pos    = (const float*)d_in[2];
    const float* ln1_s  = (const float*)d_in[3];
    const float* ln1_b  = (const float*)d_in[4];
    const float* wq     = (const float*)d_in[5];
    const float* wk     = (const float*)d_in[6];
    const float* wv     = (const float*)d_in[7];
    const float* wo     = (const float*)d_in[8];
    const float* bo     = (const float*)d_in[9];
    const float* ln2_s  = (const float*)d_in[10];
    const float* ln2_b  = (const float*)d_in[11];
    const float* w1     = (const float*)d_in[12];
    const float* b1     = (const float*)d_in[13];
    const float* w2     = (const float*)d_in[14];
    const float* b2     = (const float*)d_in[15];
    const float* lnf_s  = (const float*)d_in[16];
    const float* lnf_b  = (const float*)d_in[17];
    const float* head_w = (const float*)d_in[18];
    const float* head_b = (const float*)d_in[19];
    float* out = (float*)d_out;

    float *x, *q, *k, *v;
    __half *ah, *al, *fh, *wh, *hwh;
    cudaGetSymbolAddress((void**)&x,   g_x);
    cudaGetSymbolAddress((void**)&q,   g_q);
    cudaGetSymbolAddress((void**)&k,   g_k);
    cudaGetSymbolAddress((void**)&v,   g_v);
    cudaGetSymbolAddress((void**)&ah,  g_ah);
    cudaGetSymbolAddress((void**)&al,  g_al);
    cudaGetSymbolAddress((void**)&fh,  g_fh);
    cudaGetSymbolAddress((void**)&wh,  g_wh);
    cudaGetSymbolAddress((void**)&hwh, g_hwh);

    const int SMEM_DUAL   = GemmSmem<true>::TOTAL;    // 61440
    const int SMEM_SINGLE = GemmSmem<false>::TOTAL;   // 40960
    const int attn_smem   = 2 * KCH * HD_ * (int)sizeof(float);  // 65536

    cudaFuncSetAttribute(attn_kernel,
                         cudaFuncAttributeMaxDynamicSharedMemorySize, attn_smem);
    cudaFuncSetAttribute((const void*)mma_gemm<false, false, false, false, false>,
                         cudaFuncAttributeMaxDynamicSharedMemorySize, SMEM_SINGLE);
    cudaFuncSetAttribute((const void*)mma_gemm<true, false, true, false, false>,
                         cudaFuncAttributeMaxDynamicSharedMemorySize, SMEM_SINGLE);
    cudaFuncSetAttribute((const void*)mma_gemm<true, true, false, true, false>,
                         cudaFuncAttributeMaxDynamicSharedMemorySize, SMEM_SINGLE);
    cudaFuncSetAttribute((const void*)mma_gemm<true, false, false, false, true>,
                         cudaFuncAttributeMaxDynamicSharedMemorySize, SMEM_DUAL);

    // [0] one-launch weight prep
    prep_kernel<<<TILES_TOTAL, dim3(32, 8)>>>(wq, wk, wv, wo, w1, w2, head_w,
                                              wh, hwh);
    // [1] embedding
    embed_kernel<<<(NTOK * D_ + 255) / 256, 256>>>(idx, tok, pos, x);

    for (int l = 0; l < L_; l++) {
        const __half* WH = wh + (size_t)l * S_LAYER;
        const float* Bo = bo + (size_t)l * D_;
        const float* B1 = b1 + (size_t)l * FF_;
        const float* B2 = b2 + (size_t)l * D_;

        // ln1 + split (hi only: QKV single-A)
        lnsplit_kernel<false><<<NTOK, 128>>>(x, ln1_s + (size_t)l * D_,
                                             ln1_b + (size_t)l * D_, ah, al);
        // fused QKV (N=1152), single-A
        mma_gemm<false, false, false, false, false><<<dim3(9, 256), 256, SMEM_SINGLE>>>(
            NTOK, 3 * D_, D_, ah, nullptr, WH + OFF_QKV, nullptr,
            q, k, v, D_, D_, 3 * D_, nullptr);
        // attention -> ah (hi only); 2 CTAs per (b,h)
        attn_kernel<<<B_ * H_ * 2, 128, attn_smem>>>(q, k, v, ah);
        // x += attn @ Wo + Bo (single-A)
        mma_gemm<true, false, true, false, false><<<dim3(3, 256), 256, SMEM_SINGLE>>>(
            NTOK, D_, D_, ah, nullptr, WH + OFF_WO, Bo,
            x, x, x, D_, D_, D_, nullptr);
        // ln2 + split (hi only: W1 single-A)
        lnsplit_kernel<false><<<NTOK, 128>>>(x, ln2_s + (size_t)l * D_,
                                             ln2_b + (size_t)l * D_, ah, al);
        // ffn = relu(h @ W1 + B1) -> single fp16 (single-A)
        mma_gemm<true, true, false, true, false><<<dim3(12, 256), 256, SMEM_SINGLE>>>(
            NTOK, FF_, D_, ah, nullptr, WH + OFF_W1, B1,
            x, x, x, FF_, FF_, FF_, fh);
        // x += ffn @ W2 + B2 (single-A)
        mma_gemm<true, false, true, false, false><<<dim3(3, 256), 256, SMEM_SINGLE>>>(
            NTOK, D_, FF_, fh, nullptr, WH + OFF_W2, B2,
            x, x, x, D_, D_, D_, nullptr);
    }

    // final layernorm + split (dual: head stays dual-A for output accuracy)
    lnsplit_kernel<true><<<NTOK, 128>>>(x, lnf_s, lnf_b, ah, al);
    mma_gemm<true, false, false, false, true><<<dim3(1, 256), 256, SMEM_DUAL>>>(
        NTOK, 128, D_, ah, al, hwh, head_b,
        out, out, out, 128, V_, V_, nullptr);
}

// round 14
// speedup vs baseline: 1.6556x; 1.0440x over previous
#include <cuda_runtime.h>
#include <cuda_bf16.h>
#include <cuda_fp16.h>
#include <cstdint>

// Problem constants
#define B_    128
#define T_    256
#define D_    384
#define H_    6
#define HD_   64
#define L_    6
#define FF_   1536
#define V_    95
#define NTOK  (B_ * T_)   // 32768

extern __shared__ char dyn_smem[];

// ---------------------------------------------------------------------------
// Baseline-PTX helpers
// ---------------------------------------------------------------------------
__device__ __forceinline__ uint32_t smem_u32(const void* p) {
    uint32_t a;
    asm("{ .reg .u64 t; cvta.to.shared.u64 t, %1; cvt.u32.u64 %0, t; }"
        : "=r"(a) : "l"(p));
    return a;
}
__device__ __forceinline__ void cp16(uint32_t dst, const void* src) {
    asm volatile("cp.async.cg.shared.global [%0], [%1], 16;"
                 :: "r"(dst), "l"(src));
}
#define CP_COMMIT() asm volatile("cp.async.commit_group;" ::: "memory")
#define CP_WAIT0()  asm volatile("cp.async.wait_group 0;" ::: "memory")
#define CP_WAIT1()  asm volatile("cp.async.wait_group 1;" ::: "memory")
#define CP_WAIT2()  asm volatile("cp.async.wait_group 2;" ::: "memory")

// m16n8k16 fp16 MMA, fp32 accumulate
__device__ __forceinline__ void mma16816(float* c, const uint32_t* a,
                                         const uint32_t* b) {
    asm volatile(
        "mma.sync.aligned.m16n8k16.row.col.f32.f16.f16.f32 "
        "{%0,%1,%2,%3},{%4,%5,%6,%7},{%8,%9},{%0,%1,%2,%3};"
        : "+f"(c[0]), "+f"(c[1]), "+f"(c[2]), "+f"(c[3])
        : "r"(a[0]), "r"(a[1]), "r"(a[2]), "r"(a[3]),
          "r"(b[0]), "r"(b[1]));
}
__device__ __forceinline__ void ldsm4(uint32_t& r0, uint32_t& r1,
                                      uint32_t& r2, uint32_t& r3, uint32_t a) {
    asm volatile("ldmatrix.sync.aligned.m8n8.x4.shared.b16 {%0,%1,%2,%3}, [%4];"
                 : "=r"(r0), "=r"(r1), "=r"(r2), "=r"(r3) : "r"(a));
}

// ---------------------------------------------------------------------------
// Weight layout (per layer, packed fp16, transposed [N][K]):
// QKV[3D x D] | WO[D x D] | W1[FF x D] | W2[D x FF]
// ---------------------------------------------------------------------------
#define S_LAYER (4 * D_ * D_ + 2 * D_ * FF_)
#define OFF_QKV 0
#define OFF_WO  (3 * D_ * D_)
#define OFF_W1  (4 * D_ * D_)
#define OFF_W2  (4 * D_ * D_ + FF_ * D_)
#define WTOT    (L_ * S_LAYER)
#define HWPAD   (128 * D_)

__device__ float g_x[NTOK * D_];
__device__ float g_q[NTOK * D_];
__device__ float g_k[NTOK * D_];
__device__ float g_v[NTOK * D_];
__device__ __half g_ah[NTOK * D_],  g_al[NTOK * D_];
__device__ __half g_fh[NTOK * FF_];          // FFN intermediate: single fp16
__device__ __half g_wh[WTOT];
__device__ __half g_hwh[HWPAD];

// ---------------------------------------------------------------------------
// Embedding
// ---------------------------------------------------------------------------
__global__ void embed_kernel(const int* __restrict__ idx,
                             const float* __restrict__ tok,
                             const float* __restrict__ pos,
                             float* __restrict__ x)
{
    int i = blockIdx.x * blockDim.x + threadIdx.x;
    if (i >= NTOK * D_) return;
    int d   = i % D_;
    int row = i / D_;
    int t   = row % T_;
    int tk  = idx[row];
    x[i] = tok[tk * D_ + d] + pos[t * D_ + d];
}

// ---------------------------------------------------------------------------
// Unified weight prep: transpose + fp16 convert, ONE launch.
// Per-layer tiles: qkv 432 | wo 144 | w1 576 | w2 576 -> 1728; +48 head tiles.
// ---------------------------------------------------------------------------
#define TILES_PER_LAYER 1728
#define TILES_WEIGHTS   (L_ * TILES_PER_LAYER)
#define TILES_TOTAL     (TILES_WEIGHTS + 48)

__global__ void prep_kernel(const float* __restrict__ wq,
                            const float* __restrict__ wk,
                            const float* __restrict__ wv,
                            const float* __restrict__ wo,
                            const float* __restrict__ w1,
                            const float* __restrict__ w2,
                            const float* __restrict__ head_w,
                            __half* __restrict__ wh,
                            __half* __restrict__ hwh)
{
    __shared__ float t[32][33];
    int bid = blockIdx.x;
    int tx = threadIdx.x, ty = threadIdx.y;

    const float* W; __half* out;
    int Kd, Nd, n0, k0, nlim;

    if (bid < TILES_WEIGHTS) {
        int layer = bid / TILES_PER_LAYER;
        int r     = bid % TILES_PER_LAYER;
        size_t lw = (size_t)layer * S_LAYER;
        if (r < 432) {                       // wq / wk / wv (144 each)
            int g = r / 144, tt = r % 144;
            W   = (g == 0 ? wq : g == 1 ? wk : wv) + (size_t)layer * D_ * D_;
            out = wh + lw + (size_t)g * D_ * D_;
            Kd = D_; Nd = D_; n0 = (tt % 12) * 32; k0 = (tt / 12) * 32;
        } else if (r < 576) {                // wo (144)
            int tt = r - 432;
            W   = wo + (size_t)layer * D_ * D_;
            out = wh + lw + OFF_WO;
            Kd = D_; Nd = D_; n0 = (tt % 12) * 32; k0 = (tt / 12) * 32;
        } else if (r < 1152) {               // w1 [D x FF] -> [FF x D] (576)
            int tt = r - 576;
            W   = w1 + (size_t)layer * D_ * FF_;
            out = wh + lw + OFF_W1;
            Kd = D_; Nd = FF_; n0 = (tt % 48) * 32; k0 = (tt / 48) * 32;
        } else {                             // w2 [FF x D] -> [D x FF] (576)
            int tt = r - 1152;
            W   = w2 + (size_t)layer * D_ * FF_;
            out = wh + lw + OFF_W2;
            Kd = FF_; Nd = D_; n0 = (tt % 12) * 32; k0 = (tt / 12) * 32;
        }
        nlim = Nd;
    } else {                                 // head: W[D][V] -> [128][D] padded
        int tt = bid - TILES_WEIGHTS;
        W   = head_w;
        out = hwh;
        Kd = D_; Nd = V_; n0 = (tt % 4) * 32; k0 = (tt / 4) * 32;
        nlim = V_;
    }

    for (int r2 = ty; r2 < 32; r2 += 8) {
        int n = n0 + tx;
        t[r2][tx] = (n < nlim) ? W[(size_t)(k0 + r2) * Nd + n] : 0.0f;
    }
    __syncthreads();
    for (int r2 = ty; r2 < 32; r2 += 8) {
        float v = t[tx][r2];
        out[(size_t)(n0 + r2) * Kd + k0 + tx] = __float2half(v);
    }
}

// ---------------------------------------------------------------------------
// Fused LayerNorm + fp16 split; WRITELO controls whether lo-half is stored.
// ---------------------------------------------------------------------------
template<bool WRITELO>
__global__ void __launch_bounds__(128)
lnsplit_kernel(const float* __restrict__ x,
               const float* __restrict__ gam,
               const float* __restrict__ beta,
               __half* __restrict__ hi,
               __half* __restrict__ lo)
{
    int row = blockIdx.x;
    int tid = threadIdx.x;
    const float* xr = x + (size_t)row * D_;

    float v0 = xr[tid];
    float v1 = xr[tid + 128];
    float v2 = xr[tid + 256];

    float s  = v0 + v1 + v2;
    float sq = v0 * v0 + v1 * v1 + v2 * v2;

    #pragma unroll
    for (int off = 16; off > 0; off >>= 1) {
        s  += __shfl_xor_sync(0xffffffffu, s,  off);
        sq += __shfl_xor_sync(0xffffffffu, sq, off);
    }
    __shared__ float ss[4], ssq[4];
    int w = tid >> 5;
    if ((tid & 31) == 0) { ss[w] = s; ssq[w] = sq; }
    __syncthreads();
    s  = ss[0]  + ss[1]  + ss[2]  + ss[3];
    sq = ssq[0] + ssq[1] + ssq[2] + ssq[3];

    const float invn = 1.0f / (float)D_;
    float mean = s * invn;
    float var  = sq * invn - mean * mean;
    float inv  = rsqrtf(var + 1e-5f);

    __half* hp = hi + (size_t)row * D_;
    __half* lp = lo + (size_t)row * D_;
    #pragma unroll
    for (int e = 0; e < 3; e++) {
        int   i2 = tid + e * 128;
        float vv = (e == 0) ? v0 : (e == 1) ? v1 : v2;
        float y  = (vv - mean) * inv * gam[i2] + beta[i2];
        __half h = __float2half(y);
        hp[i2] = h;
        if (WRITELO)
            lp[i2] = __float2half(y - __half2float(h));
    }
}

// ---------------------------------------------------------------------------
// mma.sync GEMM, ldmatrix loads. DUALA: A = Ah+Al (2 products) or Ah only (1).
// 128x128 CTA tile, BK=32, 8 warps (4x2), warp tile 32x64.
// 4-stage cp.async pipeline, ONE barrier per iteration (buffer reused only
// after 2 intervening barriers -> provably race-free).
// smem rows: 64B data + 16B pad = 80B (conflict-free ldmatrix).
// ---------------------------------------------------------------------------
#define BKG      32
#define ROWB     80
#define TILE_B   (128 * ROWB)      // 10240
#define NSTAGE   4

template<bool DUALA>
struct GemmSmem { static constexpr int NT = DUALA ? 3 : 2;
                  static constexpr int STAGE = NT * TILE_B;
                  static constexpr int TOTAL = NSTAGE * NT * TILE_B; };

template<bool BIAS, bool RELU, bool RESID, bool SPLITOUT, bool DUALA>
__global__ void __launch_bounds__(256, 2)
mma_gemm(int M, int N, int K,
         const __half* __restrict__ Ah,
         const __half* __restrict__ Al,
         const __half* __restrict__ Bh,   // [N,K]
         const float* __restrict__ bias,
         float* __restrict__ C0, float* __restrict__ C1, float* __restrict__ C2,
         int nsplit, int ldc, int nmax,
         __half* __restrict__ oh)
{
    constexpr int NT      = GemmSmem<DUALA>::NT;
    constexpr int STAGE_B = GemmSmem<DUALA>::STAGE;

    char* smem = dyn_smem;
    const uint32_t sb = smem_u32(smem);

    const int tid  = threadIdx.x;
    const int wid  = tid >> 5;
    const int lane = tid & 31;
    const int wm   = wid & 3;
    const int wn   = wid >> 2;
    const int g    = lane >> 2;
    const int t    = lane & 3;

    const int n0 = blockIdx.x * 128;
    const int m0 = blockIdx.y * 128;

    const __half* gsrc[3];
    gsrc[0] = Ah + (size_t)m0 * K;
    gsrc[1] = DUALA ? (Al + (size_t)m0 * K) : (Bh + (size_t)n0 * K);
    gsrc[2] = Bh + (size_t)n0 * K;   // only used when DUALA

    const int KT = K / BKG;

    auto load_stage = [&](int kt, int s) {
        const uint32_t sdst = sb + s * STAGE_B;
        const int kc = kt * BKG;
        #pragma unroll
        for (int tile = 0; tile < NT; tile++) {
            const __half* gp = gsrc[tile];
            int row = tid >> 1, ch = tid & 1;
            cp16(sdst + tile * TILE_B + row * ROWB + ch * 16,
                 gp + (size_t)row * K + kc + ch * 8);
            cp16(sdst + tile * TILE_B + row * ROWB + (ch + 2) * 16,
                 gp + (size_t)row * K + kc + (ch + 2) * 8);
        }
    };

    float acc[2][8][4];
    #pragma unroll
    for (int i = 0; i < 2; i++)
        #pragma unroll
        for (int j = 0; j < 8; j++)
            #pragma unroll
            for (int c = 0; c < 4; c++) acc[i][j][c] = 0.0f;

    const uint32_t aOff = (uint32_t)((wm * 32 + (lane & 15)) * ROWB +
                                     ((lane >> 4) & 1) * 16);
    const uint32_t bOff = (uint32_t)((wn * 64 + (lane & 7) +
                                      ((lane >> 4) & 1) * 8) * ROWB +
                                     ((lane >> 3) & 1) * 16);

    // prologue: prefetch stages 0 and 1
    load_stage(0, 0);
    CP_COMMIT();
    load_stage(1, 1);
    CP_COMMIT();

    for (int kt = 0; kt < KT; kt++) {
        const int s = kt & (NSTAGE - 1);
        if (kt + 2 < KT) {
            load_stage(kt + 2, (kt + 2) & (NSTAGE - 1));
            CP_COMMIT();
            CP_WAIT2();          // stage kt guaranteed resident
        } else if (kt + 1 < KT) {
            CP_WAIT1();
        } else {
            CP_WAIT0();
        }
        __syncthreads();         // single barrier per iteration

        const uint32_t base   = sb + s * STAGE_B;
        const uint32_t aBaseH = base + aOff;
        const uint32_t aBaseL = base + TILE_B + aOff;          // DUALA only
        const uint32_t bBaseH = base + (NT - 1) * TILE_B + bOff;

        #pragma unroll
        for (int ks = 0; ks < 2; ks++) {
            uint32_t ah[2][4], al[2][4];
            #pragma unroll
            for (int i = 0; i < 2; i++) {
                ldsm4(ah[i][0], ah[i][1], ah[i][2], ah[i][3],
                      aBaseH + i * (16 * ROWB) + ks * 32);
                if (DUALA)
                    ldsm4(al[i][0], al[i][1], al[i][2], al[i][3],
                          aBaseL + i * (16 * ROWB) + ks * 32);
            }
            #pragma unroll
            for (int half = 0; half < 2; half++) {
                uint32_t bhr[8];
                ldsm4(bhr[0], bhr[1], bhr[2], bhr[3],
                      bBaseH + (half * 32) * ROWB + ks * 32);
                ldsm4(bhr[4], bhr[5], bhr[6], bhr[7],
                      bBaseH + (half * 32 + 16) * ROWB + ks * 32);
                #pragma unroll
                for (int i = 0; i < 2; i++)
                    #pragma unroll
                    for (int j4 = 0; j4 < 4; j4++)
                        mma16816(acc[i][half * 4 + j4], ah[i], &bhr[2 * j4]);
                if (DUALA) {
                    #pragma unroll
                    for (int i = 0; i < 2; i++)
                        #pragma unroll
                        for (int j4 = 0; j4 < 4; j4++)
                            mma16816(acc[i][half * 4 + j4], al[i], &bhr[2 * j4]);
                }
            }
        }
        // no trailing barrier: next overwrite of this buffer is 2 barriers away
    }

    // ---- epilogue ----
    const int which = n0 / nsplit;
    const int ncol0 = n0 - which * nsplit;
    float* Cb = (which == 0) ? C0 : (which == 1) ? C1 : C2;

    #pragma unroll
    for (int i = 0; i < 2; i++) {
        const int rm = m0 + wm * 32 + i * 16 + g;
        #pragma unroll
        for (int j = 0; j < 8; j++) {
            const int cnl = ncol0 + wn * 64 + j * 8 + 2 * t;
            const int gn  = n0    + wn * 64 + j * 8 + 2 * t;
            float v00 = acc[i][j][0], v01 = acc[i][j][1];
            float v10 = acc[i][j][2], v11 = acc[i][j][3];
            if (BIAS) {
                float b0 = (gn     < nmax) ? bias[gn]     : 0.0f;
                float b1 = (gn + 1 < nmax) ? bias[gn + 1] : 0.0f;
                v00 += b0; v01 += b1; v10 += b0; v11 += b1;
            }
            if (RELU) {
                v00 = fmaxf(v00, 0.f); v01 = fmaxf(v01, 0.f);
                v10 = fmaxf(v10, 0.f); v11 = fmaxf(v11, 0.f);
            }
            if (SPLITOUT) {
                size_t p0 = (size_t)rm * ldc + cnl;
                size_t p1 = (size_t)(rm + 8) * ldc + cnl;
                *reinterpret_cast<__half2*>(oh + p0) =
                    __half2{__float2half(v00), __float2half(v01)};
                *reinterpret_cast<__half2*>(oh + p1) =
                    __half2{__float2half(v10), __float2half(v11)};
            } else if (nmax == N) {
                float* p0 = Cb + (size_t)rm * ldc + cnl;
                float* p1 = Cb + (size_t)(rm + 8) * ldc + cnl;
                float2 w0 = make_float2(v00, v01);
                float2 w1 = make_float2(v10, v11);
                if (RESID) {
                    float2 o0 = *reinterpret_cast<const float2*>(p0);
                    float2 o1 = *reinterpret_cast<const float2*>(p1);
                    w0.x += o0.x; w0.y += o0.y;
                    w1.x += o1.x; w1.y += o1.y;
                }
                *reinterpret_cast<float2*>(p0) = w0;
                *reinterpret_cast<float2*>(p1) = w1;
            } else {
                if (gn < nmax) {
                    Cb[(size_t)rm * ldc + cnl]       = v00;
                    Cb[(size_t)(rm + 8) * ldc + cnl] = v10;
                }
                if (gn + 1 < nmax) {
                    Cb[(size_t)rm * ldc + cnl + 1]       = v01;
                    Cb[(size_t)(rm + 8) * ldc + cnl + 1] = v11;
                }
            }
        }
    }
}

// ---------------------------------------------------------------------------
// Causal attention: 2 CTAs per (b,h), 128 threads each, keys streamed in
// 128-row chunks through 64KB smem -> 3 CTAs/SM co-resident.
// ---------------------------------------------------------------------------
#define KCH 128
__global__ void __launch_bounds__(128)
attn_kernel(const float* __restrict__ q,
            const float* __restrict__ k,
            const float* __restrict__ v,
            __half* __restrict__ oh)
{
    float* smem = reinterpret_cast<float*>(dyn_smem);
    float* ks = smem;                 // [KCH][HD_]
    float* vs = smem + KCH * HD_;     // [KCH][HD_]

    const int cta  = blockIdx.x;
    const int bh   = cta >> 1;
    const int half = cta & 1;
    const int b    = bh / H_;
    const int h    = bh % H_;
    const int tid  = threadIdx.x;
    const int row  = half * KCH + tid;

    const size_t base = (size_t)(b * T_) * D_ + h * HD_;

    float qr[HD_];
    const float4* qrow = reinterpret_cast<const float4*>(q + base + (size_t)row * D_);
    #pragma unroll
    for (int d4 = 0; d4 < HD_ / 4; d4++) {
        float4 tv = qrow[d4];
        qr[d4 * 4 + 0] = tv.x; qr[d4 * 4 + 1] = tv.y;
        qr[d4 * 4 + 2] = tv.z; qr[d4 * 4 + 3] = tv.w;
    }

    float m = -1e30f, l = 0.0f;
    float o[HD_];
    #pragma unroll
    for (int d = 0; d < HD_; d++) o[d] = 0.0f;

    const float scale = 0.125f;

    for (int c = 0; c <= half; c++) {
        __syncthreads();
        {
            const int krow = c * KCH + tid;
            const float4* kr = reinterpret_cast<const float4*>(k + base + (size_t)krow * D_);
            const float4* vr = reinterpret_cast<const float4*>(v + base + (size_t)krow * D_);
            float4* ksd = reinterpret_cast<float4*>(ks + tid * HD_);
            float4* vsd = reinterpret_cast<float4*>(vs + tid * HD_);
            #pragma unroll
            for (int d4 = 0; d4 < HD_ / 4; d4++) {
                ksd[d4] = kr[d4];
                vsd[d4] = vr[d4];
            }
        }
        __syncthreads();

        const int jend = (c == half) ? tid : (KCH - 1);
        for (int jl = 0; jl <= jend; jl++) {
            const float* kj = ks + jl * HD_;
            float s0 = 0.f, s1 = 0.f, s2 = 0.f, s3 = 0.f;
            #pragma unroll
            for (int d = 0; d < HD_; d += 4) {
                s0 = fmaf(qr[d],     kj[d],     s0);
                s1 = fmaf(qr[d + 1], kj[d + 1], s1);
                s2 = fmaf(qr[d + 2], kj[d + 2], s2);
                s3 = fmaf(qr[d + 3], kj[d + 3], s3);
            }
            float s = ((s0 + s1) + (s2 + s3)) * scale;

            if (s > m) {
                float corr = __expf(m - s);
                l *= corr;
                #pragma unroll
                for (int d = 0; d < HD_; d++) o[d] *= corr;
                m = s;
            }
            float p = __expf(s - m);
            l += p;
            const float* vj = vs + jl * HD_;
            #pragma unroll
            for (int d = 0; d < HD_; d++) o[d] = fmaf(p, vj[d], o[d]);
        }
    }

    float invl = 1.0f / l;
    __half* hp = oh + base + (size_t)row * D_;
    #pragma unroll
    for (int d = 0; d < HD_; d++)
        hp[d] = __float2half(o[d] * invl);
}

// ---------------------------------------------------------------------------
// Host launcher
// ---------------------------------------------------------------------------
extern "C" void kernel_launch(void* const* d_in, const int* in_sizes, int n_in,
                              void* d_out, int out_size)
{
    const int*   idx    = (const int*)  d_in[0];
    const float* tok    = (const float*)d_in[1];
    const float* pos    = (const float*)d_in[2];
    const float* ln1_s  = (const float*)d_in[3];
    const float* ln1_b  = (const float*)d_in[4];
    const float* wq     = (const float*)d_in[5];
    const float* wk     = (const float*)d_in[6];
    const float* wv     = (const float*)d_in[7];
    const float* wo     = (const float*)d_in[8];
    const float* bo     = (const float*)d_in[9];
    const float* ln2_s  = (const float*)d_in[10];
    const float* ln2_b  = (const float*)d_in[11];
    const float* w1     = (const float*)d_in[12];
    const float* b1     = (const float*)d_in[13];
    const float* w2     = (const float*)d_in[14];
    const float* b2     = (const float*)d_in[15];
    const float* lnf_s  = (const float*)d_in[16];
    const float* lnf_b  = (const float*)d_in[17];
    const float* head_w = (const float*)d_in[18];
    const float* head_b = (const float*)d_in[19];
    float* out = (float*)d_out;

    float *x, *q, *k, *v;
    __half *ah, *al, *fh, *wh, *hwh;
    cudaGetSymbolAddress((void**)&x,   g_x);
    cudaGetSymbolAddress((void**)&q,   g_q);
    cudaGetSymbolAddress((void**)&k,   g_k);
    cudaGetSymbolAddress((void**)&v,   g_v);
    cudaGetSymbolAddress((void**)&ah,  g_ah);
    cudaGetSymbolAddress((void**)&al,  g_al);
    cudaGetSymbolAddress((void**)&fh,  g_fh);
    cudaGetSymbolAddress((void**)&wh,  g_wh);
    cudaGetSymbolAddress((void**)&hwh, g_hwh);

    const int SMEM_DUAL   = GemmSmem<true>::TOTAL;    // 122880
    const int SMEM_SINGLE = GemmSmem<false>::TOTAL;   // 81920
    const int attn_smem   = 2 * KCH * HD_ * (int)sizeof(float);  // 65536

    cudaFuncSetAttribute(attn_kernel,
                         cudaFuncAttributeMaxDynamicSharedMemorySize, attn_smem);
    cudaFuncSetAttribute((const void*)mma_gemm<false, false, false, false, false>,
                         cudaFuncAttributeMaxDynamicSharedMemorySize, SMEM_SINGLE);
    cudaFuncSetAttribute((const void*)mma_gemm<true, false, true, false, false>,
                         cudaFuncAttributeMaxDynamicSharedMemorySize, SMEM_SINGLE);
    cudaFuncSetAttribute((const void*)mma_gemm<true, true, false, true, false>,
                         cudaFuncAttributeMaxDynamicSharedMemorySize, SMEM_SINGLE);
    cudaFuncSetAttribute((const void*)mma_gemm<true, false, false, false, true>,
                         cudaFuncAttributeMaxDynamicSharedMemorySize, SMEM_DUAL);

    // [0] one-launch weight prep
    prep_kernel<<<TILES_TOTAL, dim3(32, 8)>>>(wq, wk, wv, wo, w1, w2, head_w,
                                              wh, hwh);
    // [1] embedding
    embed_kernel<<<(NTOK * D_ + 255) / 256, 256>>>(idx, tok, pos, x);

    for (int l = 0; l < L_; l++) {
        const __half* WH = wh + (size_t)l * S_LAYER;
        const float* Bo = bo + (size_t)l * D_;
        const float* B1 = b1 + (size_t)l * FF_;
        const float* B2 = b2 + (size_t)l * D_;

        // ln1 + split (hi only: QKV single-A)
        lnsplit_kernel<false><<<NTOK, 128>>>(x, ln1_s + (size_t)l * D_,
                                             ln1_b + (size_t)l * D_, ah, al);
        // fused QKV (N=1152), single-A
        mma_gemm<false, false, false, false, false><<<dim3(9, 256), 256, SMEM_SINGLE>>>(
            NTOK, 3 * D_, D_, ah, nullptr, WH + OFF_QKV, nullptr,
            q, k, v, D_, D_, 3 * D_, nullptr);
        // attention -> ah (hi only); 2 CTAs per (b,h)
        attn_kernel<<<B_ * H_ * 2, 128, attn_smem>>>(q, k, v, ah);
        // x += attn @ Wo + Bo (single-A)
        mma_gemm<true, false, true, false, false><<<dim3(3, 256), 256, SMEM_SINGLE>>>(
            NTOK, D_, D_, ah, nullptr, WH + OFF_WO, Bo,
            x, x, x, D_, D_, D_, nullptr);
        // ln2 + split (hi only: W1 single-A)
        lnsplit_kernel<false><<<NTOK, 128>>>(x, ln2_s + (size_t)l * D_,
                                             ln2_b + (size_t)l * D_, ah, al);
        // ffn = relu(h @ W1 + B1) -> single fp16 (single-A)
        mma_gemm<true, true, false, true, false><<<dim3(12, 256), 256, SMEM_SINGLE>>>(
            NTOK, FF_, D_, ah, nullptr, WH + OFF_W1, B1,
            x, x, x, FF_, FF_, FF_, fh);
        // x += ffn @ W2 + B2 (single-A)
        mma_gemm<true, false, true, false, false><<<dim3(3, 256), 256, SMEM_SINGLE>>>(
            NTOK, D_, FF_, fh, nullptr, WH + OFF_W2, B2,
            x, x, x, D_, D_, D_, nullptr);
    }

    // final layernorm + split (dual: head stays dual-A for output accuracy)
    lnsplit_kernel<true><<<NTOK, 128>>>(x, lnf_s, lnf_b, ah, al);
    mma_gemm<true, false, false, false, true><<<dim3(1, 256), 256, SMEM_DUAL>>>(
        NTOK, 128, D_, ah, al, hwh, head_b,
        out, out, out, 128, V_, V_, nullptr);
}

// round 15
// speedup vs baseline: 1.6999x; 1.0268x over previous
#include <cuda_runtime.h>
#include <cuda_bf16.h>
#include <cuda_fp16.h>
#include <cstdint>

// Problem constants
#define B_    128
#define T_    256
#define D_    384
#define H_    6
#define HD_   64
#define L_    6
#define FF_   1536
#define V_    95
#define NTOK  (B_ * T_)   // 32768

extern __shared__ char dyn_smem[];

// ---------------------------------------------------------------------------
// Baseline-PTX helpers
// ---------------------------------------------------------------------------
__device__ __forceinline__ uint32_t smem_u32(const void* p) {
    uint32_t a;
    asm("{ .reg .u64 t; cvta.to.shared.u64 t, %1; cvt.u32.u64 %0, t; }"
        : "=r"(a) : "l"(p));
    return a;
}
__device__ __forceinline__ void cp16(uint32_t dst, const void* src) {
    asm volatile("cp.async.cg.shared.global [%0], [%1], 16;"
                 :: "r"(dst), "l"(src));
}
#define CP_COMMIT() asm volatile("cp.async.commit_group;" ::: "memory")
#define CP_WAIT0()  asm volatile("cp.async.wait_group 0;" ::: "memory")
#define CP_WAIT1()  asm volatile("cp.async.wait_group 1;" ::: "memory")
#define CP_WAIT2()  asm volatile("cp.async.wait_group 2;" ::: "memory")

// m16n8k16 fp16 MMA, fp32 accumulate
__device__ __forceinline__ void mma16816(float* c, const uint32_t* a,
                                         const uint32_t* b) {
    asm volatile(
        "mma.sync.aligned.m16n8k16.row.col.f32.f16.f16.f32 "
        "{%0,%1,%2,%3},{%4,%5,%6,%7},{%8,%9},{%0,%1,%2,%3};"
        : "+f"(c[0]), "+f"(c[1]), "+f"(c[2]), "+f"(c[3])
        : "r"(a[0]), "r"(a[1]), "r"(a[2]), "r"(a[3]),
          "r"(b[0]), "r"(b[1]));
}
__device__ __forceinline__ void ldsm4(uint32_t& r0, uint32_t& r1,
                                      uint32_t& r2, uint32_t& r3, uint32_t a) {
    asm volatile("ldmatrix.sync.aligned.m8n8.x4.shared.b16 {%0,%1,%2,%3}, [%4];"
                 : "=r"(r0), "=r"(r1), "=r"(r2), "=r"(r3) : "r"(a));
}

// ---------------------------------------------------------------------------
// Weight layout (per layer, packed fp16, transposed [N][K]):
// QKV[3D x D] | WO[D x D] | W1[FF x D] | W2[D x FF]
// ---------------------------------------------------------------------------
#define S_LAYER (4 * D_ * D_ + 2 * D_ * FF_)
#define OFF_QKV 0
#define OFF_WO  (3 * D_ * D_)
#define OFF_W1  (4 * D_ * D_)
#define OFF_W2  (4 * D_ * D_ + FF_ * D_)
#define WTOT    (L_ * S_LAYER)
#define HWPAD   (128 * D_)

__device__ float g_x[NTOK * D_];
__device__ __half g_ah[NTOK * D_],  g_al[NTOK * D_];
__device__ __half g_fh[NTOK * FF_];  // FFN intermediate AND fused fp16 qkv buffer
__device__ __half g_wh[WTOT];
__device__ __half g_hwh[HWPAD];

// ---------------------------------------------------------------------------
// Embedding
// ---------------------------------------------------------------------------
__global__ void embed_kernel(const int* __restrict__ idx,
                             const float* __restrict__ tok,
                             const float* __restrict__ pos,
                             float* __restrict__ x)
{
    int i = blockIdx.x * blockDim.x + threadIdx.x;
    if (i >= NTOK * D_) return;
    int d   = i % D_;
    int row = i / D_;
    int t   = row % T_;
    int tk  = idx[row];
    x[i] = tok[tk * D_ + d] + pos[t * D_ + d];
}

// ---------------------------------------------------------------------------
// Unified weight prep: transpose + fp16 convert, ONE launch.
// ---------------------------------------------------------------------------
#define TILES_PER_LAYER 1728
#define TILES_WEIGHTS   (L_ * TILES_PER_LAYER)
#define TILES_TOTAL     (TILES_WEIGHTS + 48)

__global__ void prep_kernel(const float* __restrict__ wq,
                            const float* __restrict__ wk,
                            const float* __restrict__ wv,
                            const float* __restrict__ wo,
                            const float* __restrict__ w1,
                            const float* __restrict__ w2,
                            const float* __restrict__ head_w,
                            __half* __restrict__ wh,
                            __half* __restrict__ hwh)
{
    __shared__ float t[32][33];
    int bid = blockIdx.x;
    int tx = threadIdx.x, ty = threadIdx.y;

    const float* W; __half* out;
    int Kd, Nd, n0, k0, nlim;

    if (bid < TILES_WEIGHTS) {
        int layer = bid / TILES_PER_LAYER;
        int r     = bid % TILES_PER_LAYER;
        size_t lw = (size_t)layer * S_LAYER;
        if (r < 432) {
            int g = r / 144, tt = r % 144;
            W   = (g == 0 ? wq : g == 1 ? wk : wv) + (size_t)layer * D_ * D_;
            out = wh + lw + (size_t)g * D_ * D_;
            Kd = D_; Nd = D_; n0 = (tt % 12) * 32; k0 = (tt / 12) * 32;
        } else if (r < 576) {
            int tt = r - 432;
            W   = wo + (size_t)layer * D_ * D_;
            out = wh + lw + OFF_WO;
            Kd = D_; Nd = D_; n0 = (tt % 12) * 32; k0 = (tt / 12) * 32;
        } else if (r < 1152) {
            int tt = r - 576;
            W   = w1 + (size_t)layer * D_ * FF_;
            out = wh + lw + OFF_W1;
            Kd = D_; Nd = FF_; n0 = (tt % 48) * 32; k0 = (tt / 48) * 32;
        } else {
            int tt = r - 1152;
            W   = w2 + (size_t)layer * D_ * FF_;
            out = wh + lw + OFF_W2;
            Kd = FF_; Nd = D_; n0 = (tt % 12) * 32; k0 = (tt / 12) * 32;
        }
        nlim = Nd;
    } else {
        int tt = bid - TILES_WEIGHTS;
        W   = head_w;
        out = hwh;
        Kd = D_; Nd = V_; n0 = (tt % 4) * 32; k0 = (tt / 4) * 32;
        nlim = V_;
    }

    for (int r2 = ty; r2 < 32; r2 += 8) {
        int n = n0 + tx;
        t[r2][tx] = (n < nlim) ? W[(size_t)(k0 + r2) * Nd + n] : 0.0f;
    }
    __syncthreads();
    for (int r2 = ty; r2 < 32; r2 += 8) {
        float v = t[tx][r2];
        out[(size_t)(n0 + r2) * Kd + k0 + tx] = __float2half(v);
    }
}

// ---------------------------------------------------------------------------
// Fused LayerNorm + fp16 split; WRITELO controls whether lo-half is stored.
// ---------------------------------------------------------------------------
template<bool WRITELO>
__global__ void __launch_bounds__(128)
lnsplit_kernel(const float* __restrict__ x,
               const float* __restrict__ gam,
               const float* __restrict__ beta,
               __half* __restrict__ hi,
               __half* __restrict__ lo)
{
    int row = blockIdx.x;
    int tid = threadIdx.x;
    const float* xr = x + (size_t)row * D_;

    float v0 = xr[tid];
    float v1 = xr[tid + 128];
    float v2 = xr[tid + 256];

    float s  = v0 + v1 + v2;
    float sq = v0 * v0 + v1 * v1 + v2 * v2;

    #pragma unroll
    for (int off = 16; off > 0; off >>= 1) {
        s  += __shfl_xor_sync(0xffffffffu, s,  off);
        sq += __shfl_xor_sync(0xffffffffu, sq, off);
    }
    __shared__ float ss[4], ssq[4];
    int w = tid >> 5;
    if ((tid & 31) == 0) { ss[w] = s; ssq[w] = sq; }
    __syncthreads();
    s  = ss[0]  + ss[1]  + ss[2]  + ss[3];
    sq = ssq[0] + ssq[1] + ssq[2] + ssq[3];

    const float invn = 1.0f / (float)D_;
    float mean = s * invn;
    float var  = sq * invn - mean * mean;
    float inv  = rsqrtf(var + 1e-5f);

    __half* hp = hi + (size_t)row * D_;
    __half* lp = lo + (size_t)row * D_;
    #pragma unroll
    for (int e = 0; e < 3; e++) {
        int   i2 = tid + e * 128;
        float vv = (e == 0) ? v0 : (e == 1) ? v1 : v2;
        float y  = (vv - mean) * inv * gam[i2] + beta[i2];
        __half h = __float2half(y);
        hp[i2] = h;
        if (WRITELO)
            lp[i2] = __float2half(y - __half2float(h));
    }
}

// ---------------------------------------------------------------------------
// mma.sync GEMM, ldmatrix loads. 4-stage cp.async pipeline, 1 barrier/iter.
// ---------------------------------------------------------------------------
#define BKG      32
#define ROWB     80
#define TILE_B   (128 * ROWB)
#define NSTAGE   4

template<bool DUALA>
struct GemmSmem { static constexpr int NT = DUALA ? 3 : 2;
                  static constexpr int STAGE = NT * TILE_B;
                  static constexpr int TOTAL = NSTAGE * NT * TILE_B; };

template<bool BIAS, bool RELU, bool RESID, bool SPLITOUT, bool DUALA>
__global__ void __launch_bounds__(256, 2)
mma_gemm(int M, int N, int K,
         const __half* __restrict__ Ah,
         const __half* __restrict__ Al,
         const __half* __restrict__ Bh,   // [N,K]
         const float* __restrict__ bias,
         float* __restrict__ C0, float* __restrict__ C1, float* __restrict__ C2,
         int nsplit, int ldc, int nmax,
         __half* __restrict__ oh)
{
    constexpr int NT      = GemmSmem<DUALA>::NT;
    constexpr int STAGE_B = GemmSmem<DUALA>::STAGE;

    char* smem = dyn_smem;
    const uint32_t sb = smem_u32(smem);

    const int tid  = threadIdx.x;
    const int wid  = tid >> 5;
    const int lane = tid & 31;
    const int wm   = wid & 3;
    const int wn   = wid >> 2;
    const int g    = lane >> 2;
    const int t    = lane & 3;

    const int n0 = blockIdx.x * 128;
    const int m0 = blockIdx.y * 128;

    const __half* gsrc[3];
    gsrc[0] = Ah + (size_t)m0 * K;
    gsrc[1] = DUALA ? (Al + (size_t)m0 * K) : (Bh + (size_t)n0 * K);
    gsrc[2] = Bh + (size_t)n0 * K;

    const int KT = K / BKG;

    auto load_stage = [&](int kt, int s) {
        const uint32_t sdst = sb + s * STAGE_B;
        const int kc = kt * BKG;
        #pragma unroll
        for (int tile = 0; tile < NT; tile++) {
            const __half* gp = gsrc[tile];
            int row = tid >> 1, ch = tid & 1;
            cp16(sdst + tile * TILE_B + row * ROWB + ch * 16,
                 gp + (size_t)row * K + kc + ch * 8);
            cp16(sdst + tile * TILE_B + row * ROWB + (ch + 2) * 16,
                 gp + (size_t)row * K + kc + (ch + 2) * 8);
        }
    };

    float acc[2][8][4];
    #pragma unroll
    for (int i = 0; i < 2; i++)
        #pragma unroll
        for (int j = 0; j < 8; j++)
            #pragma unroll
            for (int c = 0; c < 4; c++) acc[i][j][c] = 0.0f;

    const uint32_t aOff = (uint32_t)((wm * 32 + (lane & 15)) * ROWB +
                                     ((lane >> 4) & 1) * 16);
    const uint32_t bOff = (uint32_t)((wn * 64 + (lane & 7) +
                                      ((lane >> 4) & 1) * 8) * ROWB +
                                     ((lane >> 3) & 1) * 16);

    load_stage(0, 0);
    CP_COMMIT();
    load_stage(1, 1);
    CP_COMMIT();

    for (int kt = 0; kt < KT; kt++) {
        const int s = kt & (NSTAGE - 1);
        if (kt + 2 < KT) {
            load_stage(kt + 2, (kt + 2) & (NSTAGE - 1));
            CP_COMMIT();
            CP_WAIT2();
        } else if (kt + 1 < KT) {
            CP_WAIT1();
        } else {
            CP_WAIT0();
        }
        __syncthreads();

        const uint32_t base   = sb + s * STAGE_B;
        const uint32_t aBaseH = base + aOff;
        const uint32_t aBaseL = base + TILE_B + aOff;
        const uint32_t bBaseH = base + (NT - 1) * TILE_B + bOff;

        #pragma unroll
        for (int ks = 0; ks < 2; ks++) {
            uint32_t ah[2][4], al[2][4];
            #pragma unroll
            for (int i = 0; i < 2; i++) {
                ldsm4(ah[i][0], ah[i][1], ah[i][2], ah[i][3],
                      aBaseH + i * (16 * ROWB) + ks * 32);
                if (DUALA)
                    ldsm4(al[i][0], al[i][1], al[i][2], al[i][3],
                          aBaseL + i * (16 * ROWB) + ks * 32);
            }
            #pragma unroll
            for (int half = 0; half < 2; half++) {
                uint32_t bhr[8];
                ldsm4(bhr[0], bhr[1], bhr[2], bhr[3],
                      bBaseH + (half * 32) * ROWB + ks * 32);
                ldsm4(bhr[4], bhr[5], bhr[6], bhr[7],
                      bBaseH + (half * 32 + 16) * ROWB + ks * 32);
                #pragma unroll
                for (int i = 0; i < 2; i++)
                    #pragma unroll
                    for (int j4 = 0; j4 < 4; j4++)
                        mma16816(acc[i][half * 4 + j4], ah[i], &bhr[2 * j4]);
                if (DUALA) {
                    #pragma unroll
                    for (int i = 0; i < 2; i++)
                        #pragma unroll
                        for (int j4 = 0; j4 < 4; j4++)
                            mma16816(acc[i][half * 4 + j4], al[i], &bhr[2 * j4]);
                }
            }
        }
    }

    // ---- epilogue ----
    const int which = n0 / nsplit;
    const int ncol0 = n0 - which * nsplit;
    float* Cb = (which == 0) ? C0 : (which == 1) ? C1 : C2;

    #pragma unroll
    for (int i = 0; i < 2; i++) {
        const int rm = m0 + wm * 32 + i * 16 + g;
        #pragma unroll
        for (int j = 0; j < 8; j++) {
            const int cnl = ncol0 + wn * 64 + j * 8 + 2 * t;
            const int gn  = n0    + wn * 64 + j * 8 + 2 * t;
            float v00 = acc[i][j][0], v01 = acc[i][j][1];
            float v10 = acc[i][j][2], v11 = acc[i][j][3];
            if (BIAS) {
                float b0 = (gn     < nmax) ? bias[gn]     : 0.0f;
                float b1 = (gn + 1 < nmax) ? bias[gn + 1] : 0.0f;
                v00 += b0; v01 += b1; v10 += b0; v11 += b1;
            }
            if (RELU) {
                v00 = fmaxf(v00, 0.f); v01 = fmaxf(v01, 0.f);
                v10 = fmaxf(v10, 0.f); v11 = fmaxf(v11, 0.f);
            }
            if (SPLITOUT) {
                size_t p0 = (size_t)rm * ldc + cnl;
                size_t p1 = (size_t)(rm + 8) * ldc + cnl;
                *reinterpret_cast<__half2*>(oh + p0) =
                    __half2{__float2half(v00), __float2half(v01)};
                *reinterpret_cast<__half2*>(oh + p1) =
                    __half2{__float2half(v10), __float2half(v11)};
            } else if (nmax == N) {
                float* p0 = Cb + (size_t)rm * ldc + cnl;
                float* p1 = Cb + (size_t)(rm + 8) * ldc + cnl;
                float2 w0 = make_float2(v00, v01);
                float2 w1 = make_float2(v10, v11);
                if (RESID) {
                    float2 o0 = *reinterpret_cast<const float2*>(p0);
                    float2 o1 = *reinterpret_cast<const float2*>(p1);
                    w0.x += o0.x; w0.y += o0.y;
                    w1.x += o1.x; w1.y += o1.y;
                }
                *reinterpret_cast<float2*>(p0) = w0;
                *reinterpret_cast<float2*>(p1) = w1;
            } else {
                if (gn < nmax) {
                    Cb[(size_t)rm * ldc + cnl]       = v00;
                    Cb[(size_t)(rm + 8) * ldc + cnl] = v10;
                }
                if (gn + 1 < nmax) {
                    Cb[(size_t)rm * ldc + cnl + 1]       = v01;
                    Cb[(size_t)(rm + 8) * ldc + cnl + 1] = v11;
                }
            }
        }
    }
}

// ---------------------------------------------------------------------------
// Causal attention: reads fused fp16 qkv[NTOK][3D]; fp32 smem tiles & math.
// 2 CTAs per (b,h), keys streamed in 128-row chunks.
// ---------------------------------------------------------------------------
#define KCH 128
__global__ void __launch_bounds__(128)
attn_kernel(const __half* __restrict__ qkv,
            __half* __restrict__ oh)
{
    float* smem = reinterpret_cast<float*>(dyn_smem);
    float* ks = smem;                 // [KCH][HD_]
    float* vs = smem + KCH * HD_;     // [KCH][HD_]

    const int cta  = blockIdx.x;
    const int bh   = cta >> 1;
    const int half = cta & 1;
    const int b    = bh / H_;
    const int h    = bh % H_;
    const int tid  = threadIdx.x;
    const int row  = half * KCH + tid;

    const int LD3 = 3 * D_;

    // load q (64 fp16 -> fp32 regs)
    float qr[HD_];
    {
        const uint4* qp = reinterpret_cast<const uint4*>(
            qkv + (size_t)(b * T_ + row) * LD3 + h * HD_);
        #pragma unroll
        for (int c8 = 0; c8 < HD_ / 8; c8++) {
            uint4 u = qp[c8];
            const __half2* hh = reinterpret_cast<const __half2*>(&u);
            #pragma unroll
            for (int e = 0; e < 4; e++) {
                float2 f = __half22float2(hh[e]);
                qr[c8 * 8 + 2 * e]     = f.x;
                qr[c8 * 8 + 2 * e + 1] = f.y;
            }
        }
    }

    float m = -1e30f, l = 0.0f;
    float o[HD_];
    #pragma unroll
    for (int d = 0; d < HD_; d++) o[d] = 0.0f;

    const float scale = 0.125f;

    for (int c = 0; c <= half; c++) {
        __syncthreads();
        {
            const int krow = c * KCH + tid;
            const size_t rb = (size_t)(b * T_ + krow) * LD3;
            const uint4* kp = reinterpret_cast<const uint4*>(qkv + rb + D_ + h * HD_);
            const uint4* vp = reinterpret_cast<const uint4*>(qkv + rb + 2 * D_ + h * HD_);
            float* ksd = ks + tid * HD_;
            float* vsd = vs + tid * HD_;
            #pragma unroll
            for (int c8 = 0; c8 < HD_ / 8; c8++) {
                uint4 uk = kp[c8];
                uint4 uv = vp[c8];
                const __half2* hk = reinterpret_cast<const __half2*>(&uk);
                const __half2* hv = reinterpret_cast<const __half2*>(&uv);
                #pragma unroll
                for (int e = 0; e < 4; e++) {
                    float2 fk = __half22float2(hk[e]);
                    float2 fv = __half22float2(hv[e]);
                    ksd[c8 * 8 + 2 * e]     = fk.x;
                    ksd[c8 * 8 + 2 * e + 1] = fk.y;
                    vsd[c8 * 8 + 2 * e]     = fv.x;
                    vsd[c8 * 8 + 2 * e + 1] = fv.y;
                }
            }
        }
        __syncthreads();

        const int jend = (c == half) ? tid : (KCH - 1);
        for (int jl = 0; jl <= jend; jl++) {
            const float* kj = ks + jl * HD_;
            float s0 = 0.f, s1 = 0.f, s2 = 0.f, s3 = 0.f;
            #pragma unroll
            for (int d = 0; d < HD_; d += 4) {
                s0 = fmaf(qr[d],     kj[d],     s0);
                s1 = fmaf(qr[d + 1], kj[d + 1], s1);
                s2 = fmaf(qr[d + 2], kj[d + 2], s2);
                s3 = fmaf(qr[d + 3], kj[d + 3], s3);
            }
            float s = ((s0 + s1) + (s2 + s3)) * scale;

            if (s > m) {
                float corr = __expf(m - s);
                l *= corr;
                #pragma unroll
                for (int d = 0; d < HD_; d++) o[d] *= corr;
                m = s;
            }
            float p = __expf(s - m);
            l += p;
            const float* vj = vs + jl * HD_;
            #pragma unroll
            for (int d = 0; d < HD_; d++) o[d] = fmaf(p, vj[d], o[d]);
        }
    }

    float invl = 1.0f / l;
    __half* hp = oh + (size_t)(b * T_ + row) * D_ + h * HD_;
    #pragma unroll
    for (int d = 0; d < HD_; d++)
        hp[d] = __float2half(o[d] * invl);
}

// ---------------------------------------------------------------------------
// Host launcher
// ---------------------------------------------------------------------------
extern "C" void kernel_launch(void* const* d_in, const int* in_sizes, int n_in,
                              void* d_out, int out_size)
{
    const int*   idx    = (const int*)  d_in[0];
    const float* tok    = (const float*)d_in[1];
    const float* pos    = (const float*)d_in[2];
    const float* ln1_s  = (const float*)d_in[3];
    const float* ln1_b  = (const float*)d_in[4];
    const float* wq     = (const float*)d_in[5];
    const float* wk     = (const float*)d_in[6];
    const float* wv     = (const float*)d_in[7];
    const float* wo     = (const float*)d_in[8];
    const float* bo     = (const float*)d_in[9];
    const float* ln2_s  = (const float*)d_in[10];
    const float* ln2_b  = (const float*)d_in[11];
    const float* w1     = (const float*)d_in[12];
    const float* b1     = (const float*)d_in[13];
    const float* w2     = (const float*)d_in[14];
    const float* b2     = (const float*)d_in[15];
    const float* lnf_s  = (const float*)d_in[16];
    const float* lnf_b  = (const float*)d_in[17];
    const float* head_w = (const float*)d_in[18];
    const float* head_b = (const float*)d_in[19];
    float* out = (float*)d_out;

    float *x;
    __half *ah, *al, *fh, *wh, *hwh;
    cudaGetSymbolAddress((void**)&x,   g_x);
    cudaGetSymbolAddress((void**)&ah,  g_ah);
    cudaGetSymbolAddress((void**)&al,  g_al);
    cudaGetSymbolAddress((void**)&fh,  g_fh);
    cudaGetSymbolAddress((void**)&wh,  g_wh);
    cudaGetSymbolAddress((void**)&hwh, g_hwh);

    const int SMEM_DUAL   = GemmSmem<true>::TOTAL;    // 122880
    const int SMEM_SINGLE = GemmSmem<false>::TOTAL;   // 81920
    const int attn_smem   = 2 * KCH * HD_ * (int)sizeof(float);  // 65536

    cudaFuncSetAttribute(attn_kernel,
                         cudaFuncAttributeMaxDynamicSharedMemorySize, attn_smem);
    cudaFuncSetAttribute((const void*)mma_gemm<false, false, false, true, false>,
                         cudaFuncAttributeMaxDynamicSharedMemorySize, SMEM_SINGLE);
    cudaFuncSetAttribute((const void*)mma_gemm<true, false, true, false, false>,
                         cudaFuncAttributeMaxDynamicSharedMemorySize, SMEM_SINGLE);
    cudaFuncSetAttribute((const void*)mma_gemm<true, true, false, true, false>,
                         cudaFuncAttributeMaxDynamicSharedMemorySize, SMEM_SINGLE);
    cudaFuncSetAttribute((const void*)mma_gemm<true, false, false, false, true>,
                         cudaFuncAttributeMaxDynamicSharedMemorySize, SMEM_DUAL);

    // [0] one-launch weight prep
    prep_kernel<<<TILES_TOTAL, dim3(32, 8)>>>(wq, wk, wv, wo, w1, w2, head_w,
                                              wh, hwh);
    // [1] embedding
    embed_kernel<<<(NTOK * D_ + 255) / 256, 256>>>(idx, tok, pos, x);

    for (int l = 0; l < L_; l++) {
        const __half* WH = wh + (size_t)l * S_LAYER;
        const float* Bo = bo + (size_t)l * D_;
        const float* B1 = b1 + (size_t)l * FF_;
        const float* B2 = b2 + (size_t)l * D_;

        // ln1 + split (hi only)
        lnsplit_kernel<false><<<NTOK, 128>>>(x, ln1_s + (size_t)l * D_,
                                             ln1_b + (size_t)l * D_, ah, al);
        // fused QKV (N=1152), single-A, fp16 fused output into fh[NTOK][1152]
        mma_gemm<false, false, false, true, false><<<dim3(9, 256), 256, SMEM_SINGLE>>>(
            NTOK, 3 * D_, D_, ah, nullptr, WH + OFF_QKV, nullptr,
            x, x, x, 3 * D_, 3 * D_, 3 * D_, fh);
        // attention: fused fp16 qkv -> ah (hi only); 2 CTAs per (b,h)
        attn_kernel<<<B_ * H_ * 2, 128, attn_smem>>>(fh, ah);
        // x += attn @ Wo + Bo (single-A)
        mma_gemm<true, false, true, false, false><<<dim3(3, 256), 256, SMEM_SINGLE>>>(
            NTOK, D_, D_, ah, nullptr, WH + OFF_WO, Bo,
            x, x, x, D_, D_, D_, nullptr);
        // ln2 + split (hi only)
        lnsplit_kernel<false><<<NTOK, 128>>>(x, ln2_s + (size_t)l * D_,
                                             ln2_b + (size_t)l * D_, ah, al);
        // ffn = relu(h @ W1 + B1) -> single fp16 (overwrites qkv buffer; dead)
        mma_gemm<true, true, false, true, false><<<dim3(12, 256), 256, SMEM_SINGLE>>>(
            NTOK, FF_, D_, ah, nullptr, WH + OFF_W1, B1,
            x, x, x, FF_, FF_, FF_, fh);
        // x += ffn @ W2 + B2 (single-A)
        mma_gemm<true, false, true, false, false><<<dim3(3, 256), 256, SMEM_SINGLE>>>(
            NTOK, D_, FF_, fh, nullptr, WH + OFF_W2, B2,
            x, x, x, D_, D_, D_, nullptr);
    }

    // final layernorm + split (dual: head stays dual-A for output accuracy)
    lnsplit_kernel<true><<<NTOK, 128>>>(x, lnf_s, lnf_b, ah, al);
    mma_gemm<true, false, false, false, true><<<dim3(1, 256), 256, SMEM_DUAL>>>(
        NTOK, 128, D_, ah, al, hwh, head_b,
        out, out, out, 128, V_, V_, nullptr);
}